// round 1
// baseline (speedup 1.0000x reference)
#include <cuda_runtime.h>

#define Bsz 128
#define Tt 256
#define Hh 200
#define G4 800
#define IN0 360
#define IN1 400
#define BT (Bsz*Tt)
#define NCLASS 2

// ---------------- device scratch (static, no allocation) ----------------
__device__ float d_x0[BT*IN0];        // embeddings concat [B*T, 360]
__device__ float d_x1[BT*IN1];        // layer0 output     [B*T, 400]
__device__ float d_rnn[BT*IN1];       // layer1 output     [B*T, 400]
__device__ float d_gf[BT*G4];         // precomputed gates fwd
__device__ float d_gb[BT*G4];         // precomputed gates bwd
__device__ float d_h[2][2][Hh*Bsz];   // [dir][buf][k*B + b]  (k-major!)
__device__ float d_hfin[2][Bsz*Hh];   // final h per dir [b*H + u]
__device__ float d_q[3][Bsz*IN1];     // queries: 0=obj_h 1=subj_h 2=glob_h
__device__ float d_att[3][Bsz*IN1];   // pooled attention outputs
__device__ volatile unsigned d_barcount;

// ---------------- helpers ----------------
__device__ __forceinline__ float sig_(float x) { return 1.f / (1.f + __expf(-x)); }
__device__ __forceinline__ float tanh_(float x) {
    float xc = fminf(fmaxf(x, -15.f), 15.f);
    float e = __expf(2.f * xc);
    return (e - 1.f) / (e + 1.f);
}

// ---------------- embedding concat ----------------
__global__ void embed_kernel(const int* __restrict__ words, const int* __restrict__ pos,
                             const int* __restrict__ ner,
                             const float* __restrict__ emb_w, const float* __restrict__ pos_w,
                             const float* __restrict__ ner_w) {
    int idx = blockIdx.x * blockDim.x + threadIdx.x;
    if (idx >= BT * IN0) return;
    int c = idx % IN0, bt = idx / IN0;
    float v;
    if (c < 300)        v = emb_w[(size_t)words[bt] * 300 + c];
    else if (c < 330)   v = pos_w[(size_t)pos[bt] * 30 + (c - 300)];
    else                v = ner_w[(size_t)ner[bt] * 30 + (c - 330)];
    d_x0[idx] = v;
}

// ---------------- SGEMM: C[M,800] = A[M,K] @ W[800,K]^T + bias ----------------
// BM=BN=128, BK=8, 256 threads, 8x8 per-thread tile.
__global__ void sgemm_bias(int asel, int dsel, const float* __restrict__ W,
                           const float* __restrict__ bias, int K) {
    const float* A = asel ? d_x1 : d_x0;
    float* C = dsel ? d_gb : d_gf;
    const int N = G4;
    __shared__ float As[8][128];
    __shared__ float Bs[8][128];
    int tid = threadIdx.x;
    int m0 = blockIdx.y * 128, n0 = blockIdx.x * 128;
    int lr = tid >> 1, lc = (tid & 1) * 4;
    int tx = tid & 15, ty = tid >> 4;
    float acc[8][8];
#pragma unroll
    for (int i = 0; i < 8; i++)
#pragma unroll
        for (int j = 0; j < 8; j++) acc[i][j] = 0.f;

    for (int k0 = 0; k0 < K; k0 += 8) {
        float4 av = *(const float4*)(A + (size_t)(m0 + lr) * K + k0 + lc);
        int nr = n0 + lr;
        float4 bv = make_float4(0.f, 0.f, 0.f, 0.f);
        if (nr < N) bv = *(const float4*)(W + (size_t)nr * K + k0 + lc);
        As[lc + 0][lr] = av.x; As[lc + 1][lr] = av.y; As[lc + 2][lr] = av.z; As[lc + 3][lr] = av.w;
        Bs[lc + 0][lr] = bv.x; Bs[lc + 1][lr] = bv.y; Bs[lc + 2][lr] = bv.z; Bs[lc + 3][lr] = bv.w;
        __syncthreads();
#pragma unroll
        for (int kk = 0; kk < 8; kk++) {
            float a[8], b[8];
            *(float4*)&a[0] = *(const float4*)&As[kk][ty * 8];
            *(float4*)&a[4] = *(const float4*)&As[kk][ty * 8 + 4];
            *(float4*)&b[0] = *(const float4*)&Bs[kk][tx * 8];
            *(float4*)&b[4] = *(const float4*)&Bs[kk][tx * 8 + 4];
#pragma unroll
            for (int i = 0; i < 8; i++)
#pragma unroll
                for (int j = 0; j < 8; j++) acc[i][j] += a[i] * b[j];
        }
        __syncthreads();
    }
#pragma unroll
    for (int i = 0; i < 8; i++) {
        int m = m0 + ty * 8 + i;
#pragma unroll
        for (int j = 0; j < 8; j++) {
            int n = n0 + tx * 8 + j;
            if (n < N) C[(size_t)m * N + n] = acc[i][j] + bias[n];
        }
    }
}

// ---------------- init: zero h buffers + barrier counter ----------------
__global__ void init_kernel() {
    int i = blockIdx.x * blockDim.x + threadIdx.x;
    if (i == 0) d_barcount = 0;
    if (i < 2 * 2 * Hh * Bsz) ((float*)d_h)[i] = 0.f;
}

// ---------------- persistent bidirectional LSTM layer ----------------
#define NPB 50
#define NBLK 100
#define SLICE 4

__device__ __forceinline__ void grid_sync_(unsigned target) {
    __threadfence();
    __syncthreads();
    if (threadIdx.x == 0) {
        atomicAdd((unsigned*)&d_barcount, 1u);
        while (d_barcount < target) {}
    }
    __syncthreads();
    __threadfence();
}

__global__ void lstm_layer(const float* __restrict__ Whhf, const float* __restrict__ Whhb,
                           const int* __restrict__ masks, int layer) {
    __shared__ float Wt[16][201];       // W_hh rows for this slice (gate*4 + uu)
    __shared__ float hs[8][128];        // h tile [kk][b]
    __shared__ float gsm[128][17];      // staged gates
    __shared__ float cs[128 * SLICE];   // cell state
    __shared__ float ms[128];           // keep mask this step

    const int tid = threadIdx.x;
    const int dir = blockIdx.x / NPB;           // 0 fwd, 1 bwd
    const int u0  = (blockIdx.x % NPB) * SLICE; // hidden slice base
    const float* G   = dir ? d_gb : d_gf;
    const float* Whh = dir ? Whhb : Whhf;
    float* out = layer ? d_rnn : d_x1;
    float* hb0 = d_h[dir][0];
    float* hb1 = d_h[dir][1];
    const int outofs = dir * Hh;

    // load W_hh slice: Wt[r][k] = Whh[(gate*H + u0+uu)*H + k], r = gate*4+uu
    for (int i = tid; i < 16 * Hh; i += 128) {
        int r = i / Hh, k = i - r * Hh;
        Wt[r][k] = Whh[(size_t)((r >> 2) * Hh + u0 + (r & 3)) * Hh + k];
    }
    for (int i = tid; i < 128 * SLICE; i += 128) cs[i] = 0.f;
    __syncthreads();

    const int rq = tid & 3;         // gate index 0..3 (i,f,g,o)
    const int bq = tid >> 2;        // 0..31
    const int b0 = bq * 4;

    for (int s = 0; s < Tt; s++) {
        const int t = dir ? (Tt - 1 - s) : s;
        const float* hcur = (s & 1) ? hb1 : hb0;
        float* hnxt = (s & 1) ? hb0 : hb1;

        // init accumulators from precomputed x-projection gates
        float acc[4][4];
#pragma unroll
        for (int i = 0; i < 4; i++) {
            float4 g4 = *(const float4*)(G + (size_t)((b0 + i) * Tt + t) * G4 + rq * Hh + u0);
            acc[i][0] = g4.x; acc[i][1] = g4.y; acc[i][2] = g4.z; acc[i][3] = g4.w;
        }

        // dot over h_prev (K = 200), tiles of 8
        for (int k0 = 0; k0 < Hh; k0 += 8) {
            __syncthreads();
            {
                // load 8x128 h tile (k-major global layout -> coalesced)
                int f4a = tid * 2;
                int kk0 = f4a >> 5, bp0 = (f4a & 31) * 4;
                *(float4*)&hs[kk0][bp0] = *(const float4*)(hcur + (size_t)(k0 + kk0) * Bsz + bp0);
                int f4b = tid * 2 + 1;
                int kk1 = f4b >> 5, bp1 = (f4b & 31) * 4;
                *(float4*)&hs[kk1][bp1] = *(const float4*)(hcur + (size_t)(k0 + kk1) * Bsz + bp1);
            }
            __syncthreads();
#pragma unroll
            for (int kk = 0; kk < 8; kk++) {
                float w0 = Wt[rq * 4 + 0][k0 + kk];
                float w1 = Wt[rq * 4 + 1][k0 + kk];
                float w2 = Wt[rq * 4 + 2][k0 + kk];
                float w3 = Wt[rq * 4 + 3][k0 + kk];
#pragma unroll
                for (int i = 0; i < 4; i++) {
                    float hv = hs[kk][b0 + i];
                    acc[i][0] += hv * w0; acc[i][1] += hv * w1;
                    acc[i][2] += hv * w2; acc[i][3] += hv * w3;
                }
            }
        }

        // stage gates + mask
#pragma unroll
        for (int i = 0; i < 4; i++)
#pragma unroll
            for (int j = 0; j < 4; j++) gsm[b0 + i][rq * 4 + j] = acc[i][j];
        ms[tid] = (masks[tid * Tt + t] == 0) ? 1.f : 0.f;
        __syncthreads();

        // cell update: 512 (b,uu) pairs
#pragma unroll
        for (int p = 0; p < 4; p++) {
            int j = tid + 128 * p;
            int b = j >> 2, uu = j & 3;
            float iv = sig_(gsm[b][uu]);
            float fv = sig_(gsm[b][4 + uu]);
            float gv = tanh_(gsm[b][8 + uu]);
            float ov = sig_(gsm[b][12 + uu]);
            float m  = ms[b];
            float cold = cs[j];
            float cn = fv * cold + iv * gv;
            float hn = ov * tanh_(cn);
            float hold = hcur[(size_t)(u0 + uu) * Bsz + b];
            float hnew = m * hn + (1.f - m) * hold;
            cs[j] = m * cn + (1.f - m) * cold;
            hnxt[(size_t)(u0 + uu) * Bsz + b] = hnew;
            out[(size_t)(b * Tt + t) * IN1 + outofs + u0 + uu] = m * hn;
            if (layer && s == Tt - 1) d_hfin[dir][b * Hh + u0 + uu] = hnew;
        }

        grid_sync_((unsigned)NBLK * (s + 1));
    }
}

// ---------------- span sums + queries ----------------
__global__ void span_kernel(const int* __restrict__ masks, const int* __restrict__ subj,
                            const int* __restrict__ obj) {
    int b = blockIdx.x;
    __shared__ float ssel[Tt];
    __shared__ float osel[Tt];
    for (int t = threadIdx.x; t < Tt; t += blockDim.x) {
        int m = masks[b * Tt + t];
        ssel[t] = (subj[b * Tt + t] + m == 0) ? 1.f : 0.f;
        osel[t] = (obj[b * Tt + t] + m == 0) ? 1.f : 0.f;
    }
    __syncthreads();
    for (int f = threadIdx.x; f < IN1; f += blockDim.x) {
        float ss = 0.f, os = 0.f;
        for (int t = 0; t < Tt; t++) {
            float v = d_rnn[(size_t)(b * Tt + t) * IN1 + f];
            ss += v * ssel[t];
            os += v * osel[t];
        }
        d_q[0][b * IN1 + f] = os;   // obj_h
        d_q[1][b * IN1 + f] = ss;   // subj_h
        d_q[2][b * IN1 + f] = (f < Hh) ? d_hfin[1][b * Hh + f]        // hb1 first
                                       : d_hfin[0][b * Hh + f - Hh];  // then hf1
    }
}

// ---------------- attention pooling (one block per (b, query)) ----------------
__global__ void attn_kernel(const int* __restrict__ masks) {
    int b = blockIdx.x / 3, qi = blockIdx.x % 3;
    __shared__ float qv[IN1];
    __shared__ float ps[Tt];
    __shared__ float red[256];
    int tid = threadIdx.x;
    for (int f = tid; f < IN1; f += 256) qv[f] = d_q[qi][b * IN1 + f];
    __syncthreads();

    const float* row = d_rnn + (size_t)(b * Tt + tid) * IN1;
    float sc = 0.f;
    for (int k = 0; k < IN1; k++) sc += qv[k] * row[k];
    sc *= 0.05f;  // 1/sqrt(400)
    if (masks[b * Tt + tid] != 0) sc = -1e9f;

    red[tid] = sc; __syncthreads();
    for (int o = 128; o; o >>= 1) { if (tid < o) red[tid] = fmaxf(red[tid], red[tid + o]); __syncthreads(); }
    float mx = red[0]; __syncthreads();
    float e = __expf(sc - mx);
    red[tid] = e; __syncthreads();
    for (int o = 128; o; o >>= 1) { if (tid < o) red[tid] += red[tid + o]; __syncthreads(); }
    float inv = 1.f / red[0];
    ps[tid] = e * inv;
    __syncthreads();

    for (int f = tid; f < IN1; f += 256) {
        float a = 0.f;
        for (int t = 0; t < Tt; t++) a += ps[t] * d_rnn[(size_t)(b * Tt + t) * IN1 + f];
        d_att[qi][b * IN1 + f] = a;
    }
}

// ---------------- final MLP head ----------------
__global__ void final_kernel(const float* __restrict__ wo_w, const float* __restrict__ wo_b,
                             const float* __restrict__ ws_w, const float* __restrict__ ws_b,
                             const float* __restrict__ wg_w, const float* __restrict__ wg_b,
                             const float* __restrict__ cls_w, const float* __restrict__ cls_b,
                             float* __restrict__ outp) {
    int b = blockIdx.x;
    __shared__ float hv[Hh];
    int j = threadIdx.x;
    if (j < Hh) {
        float a = wo_b[j] + ws_b[j] + wg_b[j];
        const float* o = &d_att[0][b * IN1];
        const float* s = &d_att[1][b * IN1];
        const float* g = &d_att[2][b * IN1];
        const float* wo = wo_w + (size_t)j * IN1;
        const float* ws = ws_w + (size_t)j * IN1;
        const float* wg = wg_w + (size_t)j * IN1;
        for (int k = 0; k < IN1; k++)
            a += o[k] * wo[k] + s[k] * ws[k] + g[k] * wg[k];
        hv[j] = fmaxf(a, 0.f);
    }
    __syncthreads();
    if (j < 64) {
        int n = j >> 5, lane = j & 31;
        float p = 0.f;
        for (int k = lane; k < Hh; k += 32) p += hv[k] * cls_w[n * Hh + k];
        for (int o = 16; o; o >>= 1) p += __shfl_down_sync(0xffffffffu, p, o);
        if (lane == 0) outp[b * NCLASS + n] = p + cls_b[n];
    }
}

// ---------------- launcher ----------------
extern "C" void kernel_launch(void* const* d_in, const int* in_sizes, int n_in,
                              void* d_out, int out_size) {
    const int*   words    = (const int*)d_in[0];
    const int*   masks    = (const int*)d_in[1];
    const int*   pos      = (const int*)d_in[2];
    const int*   ner      = (const int*)d_in[3];
    const int*   subj_pos = (const int*)d_in[4];
    const int*   obj_pos  = (const int*)d_in[5];
    const float* emb_w    = (const float*)d_in[6];
    const float* pos_w    = (const float*)d_in[7];
    const float* ner_w    = (const float*)d_in[8];
    const float* w_ih_l0f = (const float*)d_in[9];
    const float* w_hh_l0f = (const float*)d_in[10];
    const float* b_l0f    = (const float*)d_in[11];
    const float* w_ih_l0b = (const float*)d_in[12];
    const float* w_hh_l0b = (const float*)d_in[13];
    const float* b_l0b    = (const float*)d_in[14];
    const float* w_ih_l1f = (const float*)d_in[15];
    const float* w_hh_l1f = (const float*)d_in[16];
    const float* b_l1f    = (const float*)d_in[17];
    const float* w_ih_l1b = (const float*)d_in[18];
    const float* w_hh_l1b = (const float*)d_in[19];
    const float* b_l1b    = (const float*)d_in[20];
    const float* wo_w     = (const float*)d_in[21];
    const float* wo_b     = (const float*)d_in[22];
    const float* ws_w     = (const float*)d_in[23];
    const float* ws_b     = (const float*)d_in[24];
    const float* wg_w     = (const float*)d_in[25];
    const float* wg_b     = (const float*)d_in[26];
    const float* cls_w    = (const float*)d_in[27];
    const float* cls_b    = (const float*)d_in[28];

    // 1. embeddings
    embed_kernel<<<(BT * IN0 + 255) / 256, 256>>>(words, pos, ner, emb_w, pos_w, ner_w);

    // 2. layer-0 input projections
    dim3 ggrid(7, 256);
    sgemm_bias<<<ggrid, 256>>>(0, 0, w_ih_l0f, b_l0f, IN0);
    sgemm_bias<<<ggrid, 256>>>(0, 1, w_ih_l0b, b_l0b, IN0);

    // 3. layer-0 recurrence
    init_kernel<<<(2 * 2 * Hh * Bsz + 255) / 256, 256>>>();
    lstm_layer<<<NBLK, 128>>>(w_hh_l0f, w_hh_l0b, masks, 0);

    // 4. layer-1 input projections
    sgemm_bias<<<ggrid, 256>>>(1, 0, w_ih_l1f, b_l1f, IN1);
    sgemm_bias<<<ggrid, 256>>>(1, 1, w_ih_l1b, b_l1b, IN1);

    // 5. layer-1 recurrence (records final hidden states)
    init_kernel<<<(2 * 2 * Hh * Bsz + 255) / 256, 256>>>();
    lstm_layer<<<NBLK, 128>>>(w_hh_l1f, w_hh_l1b, masks, 1);

    // 6. span sums + queries
    span_kernel<<<Bsz, 256>>>(masks, subj_pos, obj_pos);

    // 7. attention pooling
    attn_kernel<<<Bsz * 3, 256>>>(masks);

    // 8. final head
    final_kernel<<<Bsz, 256>>>(wo_w, wo_b, ws_w, ws_b, wg_w, wg_b, cls_w, cls_b,
                               (float*)d_out);
}

// round 2
// speedup vs baseline: 1.1031x; 1.1031x over previous
#include <cuda_runtime.h>
#include <cstdint>

#define Bsz 128
#define Tt 256
#define Hh 200
#define G4 800
#define IN0 360
#define IN1 400
#define BT (Bsz*Tt)
#define NCLASS 2

// ---------------- device scratch (static, no allocation) ----------------
__device__ float d_x0[BT*IN0];        // embeddings concat [B*T, 360]
__device__ float d_x1[BT*IN1];        // layer0 output     [B*T, 400]
__device__ float d_rnn[BT*IN1];       // layer1 output     [B*T, 400]
__device__ float d_gf[BT*G4];         // precomputed gates fwd
__device__ float d_gb[BT*G4];         // precomputed gates bwd
__device__ float d_h[2][2][Hh*Bsz];   // [dir][buf][k*B + b]  (k-major!)
__device__ float d_hfin[2][Bsz*Hh];   // final h per dir [b*H + u]
__device__ float d_q[3][Bsz*IN1];     // queries: 0=obj_h 1=subj_h 2=glob_h
__device__ float d_att[3][Bsz*IN1];   // pooled attention outputs
__device__ volatile unsigned d_barcount;

// ---------------- helpers ----------------
__device__ __forceinline__ float sig_(float x) { return 1.f / (1.f + __expf(-x)); }
__device__ __forceinline__ float tanh_(float x) {
    float xc = fminf(fmaxf(x, -15.f), 15.f);
    float e = __expf(2.f * xc);
    return (e - 1.f) / (e + 1.f);
}
__device__ __forceinline__ float to_tf32(float x) {
    float r;
    asm("cvt.rna.tf32.f32 %0, %1;" : "=f"(r) : "f"(x));
    return r;
}
__device__ __forceinline__ void mma_tf32(float* d, const uint32_t* a, const uint32_t* b) {
    asm volatile(
        "mma.sync.aligned.m16n8k8.row.col.f32.tf32.tf32.f32 "
        "{%0,%1,%2,%3}, {%4,%5,%6,%7}, {%8,%9}, {%0,%1,%2,%3};"
        : "+f"(d[0]), "+f"(d[1]), "+f"(d[2]), "+f"(d[3])
        : "r"(a[0]), "r"(a[1]), "r"(a[2]), "r"(a[3]), "r"(b[0]), "r"(b[1]));
}

// ---------------- embedding concat ----------------
__global__ void embed_kernel(const int* __restrict__ words, const int* __restrict__ pos,
                             const int* __restrict__ ner,
                             const float* __restrict__ emb_w, const float* __restrict__ pos_w,
                             const float* __restrict__ ner_w) {
    int idx = blockIdx.x * blockDim.x + threadIdx.x;
    if (idx >= BT * IN0) return;
    int c = idx % IN0, bt = idx / IN0;
    float v;
    if (c < 300)        v = emb_w[(size_t)words[bt] * 300 + c];
    else if (c < 330)   v = pos_w[(size_t)pos[bt] * 30 + (c - 300)];
    else                v = ner_w[(size_t)ner[bt] * 30 + (c - 330)];
    d_x0[idx] = v;
}

// ---------------- TF32 tensor-core GEMM ----------------
// C[M=32768, 800] = A[M,K] @ W[800,K]^T + bias
// BM=128, BN=160, BK=8, 256 threads (8 warps, 2x4), warp tile 64x40,
// mma.m16n8k8 frags: 4 (m) x 5 (n). Double-buffered smem, pad-12 rows
// (conflict-free for the fragment LDS pattern).
#define GBM 128
#define GBN 160
#define GBK 8
#define GPAD 12

__global__ __launch_bounds__(256, 1)
void gemm_tf32(int asel, int dsel, const float* __restrict__ W,
               const float* __restrict__ bias, int K) {
    const float* A = asel ? d_x1 : d_x0;
    float* C = dsel ? d_gb : d_gf;

    __shared__ __align__(16) float As[2][GBM][GPAD];
    __shared__ __align__(16) float Bs[2][GBN][GPAD];

    const int tid = threadIdx.x;
    const int lane = tid & 31;
    const int w = tid >> 5;
    const int wm = w & 1;          // 0..1 -> m base wm*64
    const int wn = w >> 1;         // 0..3 -> n base wn*40
    const int g = lane >> 2, tg = lane & 3;

    const int m0 = blockIdx.y * GBM;
    const int n0 = blockIdx.x * GBN;

    // global load indices
    const int arow = tid >> 1, acol = (tid & 1) * 4;
    const int b_i0 = tid;                 // < 320
    const int b_i1 = tid + 256;           // < 320 only for tid<64
    const int brow0 = b_i0 >> 1, bcol0 = (b_i0 & 1) * 4;
    const int brow1 = b_i1 >> 1, bcol1 = (b_i1 & 1) * 4;

    float acc[4][5][4];
#pragma unroll
    for (int i = 0; i < 4; i++)
#pragma unroll
        for (int j = 0; j < 5; j++)
#pragma unroll
            for (int r = 0; r < 4; r++) acc[i][j][r] = 0.f;

    const int niter = K / GBK;

    // prologue: load tile 0
    float4 ar = *(const float4*)(A + (size_t)(m0 + arow) * K + acol);
    float4 br0 = *(const float4*)(W + (size_t)(n0 + brow0) * K + bcol0);
    float4 br1 = make_float4(0.f, 0.f, 0.f, 0.f);
    if (b_i1 < 320) br1 = *(const float4*)(W + (size_t)(n0 + brow1) * K + bcol1);

    As[0][arow][acol + 0] = to_tf32(ar.x); As[0][arow][acol + 1] = to_tf32(ar.y);
    As[0][arow][acol + 2] = to_tf32(ar.z); As[0][arow][acol + 3] = to_tf32(ar.w);
    Bs[0][brow0][bcol0 + 0] = to_tf32(br0.x); Bs[0][brow0][bcol0 + 1] = to_tf32(br0.y);
    Bs[0][brow0][bcol0 + 2] = to_tf32(br0.z); Bs[0][brow0][bcol0 + 3] = to_tf32(br0.w);
    if (b_i1 < 320) {
        Bs[0][brow1][bcol1 + 0] = to_tf32(br1.x); Bs[0][brow1][bcol1 + 1] = to_tf32(br1.y);
        Bs[0][brow1][bcol1 + 2] = to_tf32(br1.z); Bs[0][brow1][bcol1 + 3] = to_tf32(br1.w);
    }
    __syncthreads();

    for (int it = 0; it < niter; it++) {
        const int cur = it & 1, nxt = cur ^ 1;
        const int k0 = (it + 1) * GBK;
        if (it + 1 < niter) {
            ar = *(const float4*)(A + (size_t)(m0 + arow) * K + k0 + acol);
            br0 = *(const float4*)(W + (size_t)(n0 + brow0) * K + k0 + bcol0);
            if (b_i1 < 320) br1 = *(const float4*)(W + (size_t)(n0 + brow1) * K + k0 + bcol1);
        }

        // fragment loads
        uint32_t afr[4][4];
#pragma unroll
        for (int mi = 0; mi < 4; mi++) {
            int m = wm * 64 + mi * 16 + g;
            afr[mi][0] = __float_as_uint(As[cur][m][tg]);
            afr[mi][1] = __float_as_uint(As[cur][m + 8][tg]);
            afr[mi][2] = __float_as_uint(As[cur][m][tg + 4]);
            afr[mi][3] = __float_as_uint(As[cur][m + 8][tg + 4]);
        }
        uint32_t bfr[5][2];
#pragma unroll
        for (int nj = 0; nj < 5; nj++) {
            int n = wn * 40 + nj * 8 + g;
            bfr[nj][0] = __float_as_uint(Bs[cur][n][tg]);
            bfr[nj][1] = __float_as_uint(Bs[cur][n][tg + 4]);
        }
#pragma unroll
        for (int mi = 0; mi < 4; mi++)
#pragma unroll
            for (int nj = 0; nj < 5; nj++)
                mma_tf32(acc[mi][nj], afr[mi], bfr[nj]);

        if (it + 1 < niter) {
            As[nxt][arow][acol + 0] = to_tf32(ar.x); As[nxt][arow][acol + 1] = to_tf32(ar.y);
            As[nxt][arow][acol + 2] = to_tf32(ar.z); As[nxt][arow][acol + 3] = to_tf32(ar.w);
            Bs[nxt][brow0][bcol0 + 0] = to_tf32(br0.x); Bs[nxt][brow0][bcol0 + 1] = to_tf32(br0.y);
            Bs[nxt][brow0][bcol0 + 2] = to_tf32(br0.z); Bs[nxt][brow0][bcol0 + 3] = to_tf32(br0.w);
            if (b_i1 < 320) {
                Bs[nxt][brow1][bcol1 + 0] = to_tf32(br1.x); Bs[nxt][brow1][bcol1 + 1] = to_tf32(br1.y);
                Bs[nxt][brow1][bcol1 + 2] = to_tf32(br1.z); Bs[nxt][brow1][bcol1 + 3] = to_tf32(br1.w);
            }
        }
        __syncthreads();
    }

    // epilogue: C = acc + bias  (N=800 exactly covered, no bounds checks)
#pragma unroll
    for (int mi = 0; mi < 4; mi++) {
        int mrow = m0 + wm * 64 + mi * 16 + g;
#pragma unroll
        for (int nj = 0; nj < 5; nj++) {
            int ncol = n0 + wn * 40 + nj * 8 + 2 * tg;
            float bx = bias[ncol], by = bias[ncol + 1];
            float2 v0 = make_float2(acc[mi][nj][0] + bx, acc[mi][nj][1] + by);
            float2 v1 = make_float2(acc[mi][nj][2] + bx, acc[mi][nj][3] + by);
            *(float2*)(C + (size_t)mrow * G4 + ncol) = v0;
            *(float2*)(C + (size_t)(mrow + 8) * G4 + ncol) = v1;
        }
    }
}

// ---------------- init: zero h buffers / barrier counter ----------------
__global__ void init_h_kernel() {
    int i = blockIdx.x * blockDim.x + threadIdx.x;
    if (i < 2 * 2 * Hh * Bsz) ((float*)d_h)[i] = 0.f;
}
__global__ void init_bar_kernel() { d_barcount = 0; }

// ---------------- persistent bidirectional LSTM layer ----------------
#define NPB 50
#define NBLK 100
#define SLICE 4

__device__ __forceinline__ void grid_sync_(unsigned target) {
    __threadfence();
    __syncthreads();
    if (threadIdx.x == 0) {
        atomicAdd((unsigned*)&d_barcount, 1u);
        while (d_barcount < target) {}
    }
    __syncthreads();
    __threadfence();
}

__global__ void lstm_layer(const float* __restrict__ Whhf, const float* __restrict__ Whhb,
                           const int* __restrict__ masks, int layer) {
    __shared__ float Wt[16][201];       // W_hh rows for this slice (gate*4 + uu)
    __shared__ float hs[8][128];        // h tile [kk][b]
    __shared__ float gsm[128][17];      // staged gates
    __shared__ float cs[128 * SLICE];   // cell state
    __shared__ float ms[128];           // keep mask this step

    const int tid = threadIdx.x;
    const int dir = blockIdx.x / NPB;           // 0 fwd, 1 bwd
    const int u0  = (blockIdx.x % NPB) * SLICE; // hidden slice base
    const float* G   = dir ? d_gb : d_gf;
    const float* Whh = dir ? Whhb : Whhf;
    float* out = layer ? d_rnn : d_x1;
    float* hb0 = d_h[dir][0];
    float* hb1 = d_h[dir][1];
    const int outofs = dir * Hh;

    for (int i = tid; i < 16 * Hh; i += 128) {
        int r = i / Hh, k = i - r * Hh;
        Wt[r][k] = Whh[(size_t)((r >> 2) * Hh + u0 + (r & 3)) * Hh + k];
    }
    for (int i = tid; i < 128 * SLICE; i += 128) cs[i] = 0.f;
    __syncthreads();

    const int rq = tid & 3;
    const int bq = tid >> 2;
    const int b0 = bq * 4;

    for (int s = 0; s < Tt; s++) {
        const int t = dir ? (Tt - 1 - s) : s;
        const float* hcur = (s & 1) ? hb1 : hb0;
        float* hnxt = (s & 1) ? hb0 : hb1;

        float acc[4][4];
#pragma unroll
        for (int i = 0; i < 4; i++) {
            float4 g4 = *(const float4*)(G + (size_t)((b0 + i) * Tt + t) * G4 + rq * Hh + u0);
            acc[i][0] = g4.x; acc[i][1] = g4.y; acc[i][2] = g4.z; acc[i][3] = g4.w;
        }

        for (int k0 = 0; k0 < Hh; k0 += 8) {
            __syncthreads();
            {
                int f4a = tid * 2;
                int kk0 = f4a >> 5, bp0 = (f4a & 31) * 4;
                *(float4*)&hs[kk0][bp0] = *(const float4*)(hcur + (size_t)(k0 + kk0) * Bsz + bp0);
                int f4b = tid * 2 + 1;
                int kk1 = f4b >> 5, bp1 = (f4b & 31) * 4;
                *(float4*)&hs[kk1][bp1] = *(const float4*)(hcur + (size_t)(k0 + kk1) * Bsz + bp1);
            }
            __syncthreads();
#pragma unroll
            for (int kk = 0; kk < 8; kk++) {
                float w0 = Wt[rq * 4 + 0][k0 + kk];
                float w1 = Wt[rq * 4 + 1][k0 + kk];
                float w2 = Wt[rq * 4 + 2][k0 + kk];
                float w3 = Wt[rq * 4 + 3][k0 + kk];
#pragma unroll
                for (int i = 0; i < 4; i++) {
                    float hv = hs[kk][b0 + i];
                    acc[i][0] += hv * w0; acc[i][1] += hv * w1;
                    acc[i][2] += hv * w2; acc[i][3] += hv * w3;
                }
            }
        }

#pragma unroll
        for (int i = 0; i < 4; i++)
#pragma unroll
            for (int j = 0; j < 4; j++) gsm[b0 + i][rq * 4 + j] = acc[i][j];
        ms[tid] = (masks[tid * Tt + t] == 0) ? 1.f : 0.f;
        __syncthreads();

#pragma unroll
        for (int p = 0; p < 4; p++) {
            int j = tid + 128 * p;
            int b = j >> 2, uu = j & 3;
            float iv = sig_(gsm[b][uu]);
            float fv = sig_(gsm[b][4 + uu]);
            float gv = tanh_(gsm[b][8 + uu]);
            float ov = sig_(gsm[b][12 + uu]);
            float m  = ms[b];
            float cold = cs[j];
            float cn = fv * cold + iv * gv;
            float hn = ov * tanh_(cn);
            float hold = hcur[(size_t)(u0 + uu) * Bsz + b];
            float hnew = m * hn + (1.f - m) * hold;
            cs[j] = m * cn + (1.f - m) * cold;
            hnxt[(size_t)(u0 + uu) * Bsz + b] = hnew;
            out[(size_t)(b * Tt + t) * IN1 + outofs + u0 + uu] = m * hn;
            if (layer && s == Tt - 1) d_hfin[dir][b * Hh + u0 + uu] = hnew;
        }

        grid_sync_((unsigned)NBLK * (s + 1));
    }
}

// ---------------- span sums + queries ----------------
__global__ void span_kernel(const int* __restrict__ masks, const int* __restrict__ subj,
                            const int* __restrict__ obj) {
    int b = blockIdx.x;
    __shared__ float ssel[Tt];
    __shared__ float osel[Tt];
    for (int t = threadIdx.x; t < Tt; t += blockDim.x) {
        int m = masks[b * Tt + t];
        ssel[t] = (subj[b * Tt + t] + m == 0) ? 1.f : 0.f;
        osel[t] = (obj[b * Tt + t] + m == 0) ? 1.f : 0.f;
    }
    __syncthreads();
    for (int f = threadIdx.x; f < IN1; f += blockDim.x) {
        float ss = 0.f, os = 0.f;
        for (int t = 0; t < Tt; t++) {
            float v = d_rnn[(size_t)(b * Tt + t) * IN1 + f];
            ss += v * ssel[t];
            os += v * osel[t];
        }
        d_q[0][b * IN1 + f] = os;
        d_q[1][b * IN1 + f] = ss;
        d_q[2][b * IN1 + f] = (f < Hh) ? d_hfin[1][b * Hh + f]
                                       : d_hfin[0][b * Hh + f - Hh];
    }
}

// ---------------- attention pooling ----------------
__global__ void attn_kernel(const int* __restrict__ masks) {
    int b = blockIdx.x / 3, qi = blockIdx.x % 3;
    __shared__ float qv[IN1];
    __shared__ float ps[Tt];
    __shared__ float red[256];
    int tid = threadIdx.x;
    for (int f = tid; f < IN1; f += 256) qv[f] = d_q[qi][b * IN1 + f];
    __syncthreads();

    const float* row = d_rnn + (size_t)(b * Tt + tid) * IN1;
    float sc = 0.f;
    for (int k = 0; k < IN1; k++) sc += qv[k] * row[k];
    sc *= 0.05f;
    if (masks[b * Tt + tid] != 0) sc = -1e9f;

    red[tid] = sc; __syncthreads();
    for (int o = 128; o; o >>= 1) { if (tid < o) red[tid] = fmaxf(red[tid], red[tid + o]); __syncthreads(); }
    float mx = red[0]; __syncthreads();
    float e = __expf(sc - mx);
    red[tid] = e; __syncthreads();
    for (int o = 128; o; o >>= 1) { if (tid < o) red[tid] += red[tid + o]; __syncthreads(); }
    float inv = 1.f / red[0];
    ps[tid] = e * inv;
    __syncthreads();

    for (int f = tid; f < IN1; f += 256) {
        float a = 0.f;
        for (int t = 0; t < Tt; t++) a += ps[t] * d_rnn[(size_t)(b * Tt + t) * IN1 + f];
        d_att[qi][b * IN1 + f] = a;
    }
}

// ---------------- final MLP head ----------------
__global__ void final_kernel(const float* __restrict__ wo_w, const float* __restrict__ wo_b,
                             const float* __restrict__ ws_w, const float* __restrict__ ws_b,
                             const float* __restrict__ wg_w, const float* __restrict__ wg_b,
                             const float* __restrict__ cls_w, const float* __restrict__ cls_b,
                             float* __restrict__ outp) {
    int b = blockIdx.x;
    __shared__ float hv[Hh];
    int j = threadIdx.x;
    if (j < Hh) {
        float a = wo_b[j] + ws_b[j] + wg_b[j];
        const float* o = &d_att[0][b * IN1];
        const float* s = &d_att[1][b * IN1];
        const float* g = &d_att[2][b * IN1];
        const float* wo = wo_w + (size_t)j * IN1;
        const float* ws = ws_w + (size_t)j * IN1;
        const float* wg = wg_w + (size_t)j * IN1;
        for (int k = 0; k < IN1; k++)
            a += o[k] * wo[k] + s[k] * ws[k] + g[k] * wg[k];
        hv[j] = fmaxf(a, 0.f);
    }
    __syncthreads();
    if (j < 64) {
        int n = j >> 5, lane = j & 31;
        float p = 0.f;
        for (int k = lane; k < Hh; k += 32) p += hv[k] * cls_w[n * Hh + k];
        for (int o = 16; o; o >>= 1) p += __shfl_down_sync(0xffffffffu, p, o);
        if (lane == 0) outp[b * NCLASS + n] = p + cls_b[n];
    }
}

// ---------------- launcher ----------------
extern "C" void kernel_launch(void* const* d_in, const int* in_sizes, int n_in,
                              void* d_out, int out_size) {
    const int*   words    = (const int*)d_in[0];
    const int*   masks    = (const int*)d_in[1];
    const int*   pos      = (const int*)d_in[2];
    const int*   ner      = (const int*)d_in[3];
    const int*   subj_pos = (const int*)d_in[4];
    const int*   obj_pos  = (const int*)d_in[5];
    const float* emb_w    = (const float*)d_in[6];
    const float* pos_w    = (const float*)d_in[7];
    const float* ner_w    = (const float*)d_in[8];
    const float* w_ih_l0f = (const float*)d_in[9];
    const float* w_hh_l0f = (const float*)d_in[10];
    const float* b_l0f    = (const float*)d_in[11];
    const float* w_ih_l0b = (const float*)d_in[12];
    const float* w_hh_l0b = (const float*)d_in[13];
    const float* b_l0b    = (const float*)d_in[14];
    const float* w_ih_l1f = (const float*)d_in[15];
    const float* w_hh_l1f = (const float*)d_in[16];
    const float* b_l1f    = (const float*)d_in[17];
    const float* w_ih_l1b = (const float*)d_in[18];
    const float* w_hh_l1b = (const float*)d_in[19];
    const float* b_l1b    = (const float*)d_in[20];
    const float* wo_w     = (const float*)d_in[21];
    const float* wo_b     = (const float*)d_in[22];
    const float* ws_w     = (const float*)d_in[23];
    const float* ws_b     = (const float*)d_in[24];
    const float* wg_w     = (const float*)d_in[25];
    const float* wg_b     = (const float*)d_in[26];
    const float* cls_w    = (const float*)d_in[27];
    const float* cls_b    = (const float*)d_in[28];

    dim3 ggrid(5, 256);  // 800/160, 32768/128

    // launch order arranged so ncu (-s 5 -c 1) captures lstm_layer (index 5)
    embed_kernel<<<(BT * IN0 + 255) / 256, 256>>>(words, pos, ner, emb_w, pos_w, ner_w); // 0
    init_h_kernel<<<(2 * 2 * Hh * Bsz + 255) / 256, 256>>>();                            // 1
    init_bar_kernel<<<1, 1>>>();                                                          // 2
    gemm_tf32<<<ggrid, 256>>>(0, 0, w_ih_l0f, b_l0f, IN0);                                // 3
    gemm_tf32<<<ggrid, 256>>>(0, 1, w_ih_l0b, b_l0b, IN0);                                // 4
    lstm_layer<<<NBLK, 128>>>(w_hh_l0f, w_hh_l0b, masks, 0);                              // 5 <- ncu
    gemm_tf32<<<ggrid, 256>>>(1, 0, w_ih_l1f, b_l1f, IN1);                                // 6
    gemm_tf32<<<ggrid, 256>>>(1, 1, w_ih_l1b, b_l1b, IN1);                                // 7
    init_h_kernel<<<(2 * 2 * Hh * Bsz + 255) / 256, 256>>>();                             // 8
    init_bar_kernel<<<1, 1>>>();                                                          // 9
    lstm_layer<<<NBLK, 128>>>(w_hh_l1f, w_hh_l1b, masks, 1);                              // 10
    span_kernel<<<Bsz, 256>>>(masks, subj_pos, obj_pos);                                  // 11
    attn_kernel<<<Bsz * 3, 256>>>(masks);                                                 // 12
    final_kernel<<<Bsz, 256>>>(wo_w, wo_b, ws_w, ws_b, wg_w, wg_b, cls_w, cls_b,
                               (float*)d_out);                                            // 13
}

// round 3
// speedup vs baseline: 2.2438x; 2.0341x over previous
#include <cuda_runtime.h>
#include <cstdint>

#define Bsz 128
#define Tt 256
#define Hh 200
#define IN1 400
#define BT (Bsz*Tt)
#define NCLASS 2
#define G16 1600

// ---------------- device scratch (static, no allocation) ----------------
__device__ __align__(16) float d_x0[BT*400];      // embeddings concat, tf32, K-padded to 400
__device__ __align__(16) float d_x1[BT*400];      // layer0 output (tf32-rounded)
__device__ __align__(16) float d_rnn[BT*400];     // layer1 output (fp32)
__device__ __align__(16) float d_g[(size_t)BT*G16]; // gates: [bt][fwd 800 | bwd 800]
__device__ __align__(16) float d_h[2][2][Hh*Bsz]; // [dir][buf][u*128 + b]
__device__ __align__(16) float d_hfin[2][Bsz*Hh];
__device__ __align__(16) float d_q[3][Bsz*IN1];
__device__ __align__(16) float d_att[3][Bsz*IN1];
__device__ __align__(16) float d_wcat[2][G16*400]; // padded tf32 W_ih per layer
__device__ __align__(16) float d_bcat[2][G16];
__device__ __align__(16) float d_mt[Tt*Bsz];      // keep-mask transposed [t][b]
__device__ volatile unsigned d_barc[2];

// ---------------- helpers ----------------
__device__ __forceinline__ float sig_(float x) { return 1.f / (1.f + __expf(-x)); }
__device__ __forceinline__ float tanh_(float x) {
    float xc = fminf(fmaxf(x, -15.f), 15.f);
    float e = __expf(2.f * xc);
    return (e - 1.f) / (e + 1.f);
}
__device__ __forceinline__ float to_tf32(float x) {
    float r;
    asm("cvt.rna.tf32.f32 %0, %1;" : "=f"(r) : "f"(x));
    return r;
}
__device__ __forceinline__ void mma_tf32(float* d, const uint32_t* a, const uint32_t* b) {
    asm volatile(
        "mma.sync.aligned.m16n8k8.row.col.f32.tf32.tf32.f32 "
        "{%0,%1,%2,%3}, {%4,%5,%6,%7}, {%8,%9}, {%0,%1,%2,%3};"
        : "+f"(d[0]), "+f"(d[1]), "+f"(d[2]), "+f"(d[3])
        : "r"(a[0]), "r"(a[1]), "r"(a[2]), "r"(a[3]), "r"(b[0]), "r"(b[1]));
}
__device__ __forceinline__ void cp16(uint32_t saddr, const void* gaddr) {
    asm volatile("cp.async.cg.shared.global [%0], [%1], 16;" :: "r"(saddr), "l"(gaddr));
}

// ---------------- embedding concat (tf32-rounded, K padded to 400) ----------------
__global__ void embed_kernel(const int* __restrict__ words, const int* __restrict__ pos,
                             const int* __restrict__ ner,
                             const float* __restrict__ emb_w, const float* __restrict__ pos_w,
                             const float* __restrict__ ner_w) {
    int idx = blockIdx.x * blockDim.x + threadIdx.x;
    if (idx >= BT * 400) return;
    int c = idx % 400, bt = idx / 400;
    float v = 0.f;
    if (c < 300)        v = emb_w[(size_t)words[bt] * 300 + c];
    else if (c < 330)   v = pos_w[(size_t)pos[bt] * 30 + (c - 300)];
    else if (c < 360)   v = ner_w[(size_t)ner[bt] * 30 + (c - 330)];
    d_x0[idx] = to_tf32(v);
}

// ---------------- W_ih prep: concat fwd+bwd, pad K to 400, tf32 ----------------
__global__ void wprep_kernel(const float* __restrict__ wf, const float* __restrict__ wb,
                             const float* __restrict__ bf, const float* __restrict__ bb_,
                             int K, int layer) {
    int i = blockIdx.x * blockDim.x + threadIdx.x;
    if (i < G16 * 400) {
        int n = i / 400, k = i % 400;
        float v = 0.f;
        if (k < K) {
            const float* W = (n < 800) ? wf : wb;
            int nn = (n < 800) ? n : n - 800;
            v = to_tf32(W[(size_t)nn * K + k]);
        }
        d_wcat[layer][i] = v;
    }
    if (i < G16) d_bcat[layer][i] = (i < 800) ? bf[i] : bb_[i - 800];
}

// ---------------- TF32 GEMM: d_g[32768,1600] = A[32768,400] @ Wcat^T + bias ----
// BM=128, BN=160, BK=40, cp.async double-buffer, 256 thr, warp tile 64x40.
__global__ __launch_bounds__(256, 1)
void gemm_tf32(int asel, int layer) {
    extern __shared__ float smg[];
    float* Abuf[2] = { smg, smg + 5632 };              // 128*44 each
    float* Bbuf[2] = { smg + 11264, smg + 18304 };     // 160*44 each
    const float* A = asel ? d_x1 : d_x0;
    const float* Wc = d_wcat[layer];
    const float* bc = d_bcat[layer];

    const int tid = threadIdx.x;
    const int lane = tid & 31, w = tid >> 5;
    const int wm = w & 1, wn = w >> 1;
    const int g = lane >> 2, tg = lane & 3;
    const int m0 = blockIdx.y * 128, n0 = blockIdx.x * 160;

    uint32_t sA[2], sB[2];
    sA[0] = (uint32_t)__cvta_generic_to_shared(Abuf[0]);
    sA[1] = (uint32_t)__cvta_generic_to_shared(Abuf[1]);
    sB[0] = (uint32_t)__cvta_generic_to_shared(Bbuf[0]);
    sB[1] = (uint32_t)__cvta_generic_to_shared(Bbuf[1]);

    float acc[4][5][4];
#pragma unroll
    for (int i = 0; i < 4; i++)
#pragma unroll
        for (int j = 0; j < 5; j++)
#pragma unroll
            for (int r = 0; r < 4; r++) acc[i][j][r] = 0.f;

#define STAGE(IT, BUF) do {                                                    \
        int k0 = (IT) * 40;                                                    \
        for (int i = tid; i < 1280; i += 256) {                                \
            int row = i / 10, c4 = (i % 10) * 4;                               \
            cp16(sA[BUF] + (uint32_t)(row * 44 + c4) * 4,                      \
                 A + (size_t)(m0 + row) * 400 + k0 + c4);                      \
        }                                                                      \
        for (int i = tid; i < 1600; i += 256) {                                \
            int row = i / 10, c4 = (i % 10) * 4;                               \
            cp16(sB[BUF] + (uint32_t)(row * 44 + c4) * 4,                      \
                 Wc + (size_t)(n0 + row) * 400 + k0 + c4);                     \
        }                                                                      \
        asm volatile("cp.async.commit_group;");                                \
    } while (0)

    STAGE(0, 0);

    for (int it = 0; it < 10; it++) {
        const int cur = it & 1;
        asm volatile("cp.async.wait_group 0;");
        __syncthreads();
        if (it < 9) STAGE(it + 1, cur ^ 1);

        const float* As = Abuf[cur];
        const float* Bs = Bbuf[cur];
#pragma unroll
        for (int ks = 0; ks < 5; ks++) {
            const int kb = ks * 8;
            uint32_t afr[4][4];
#pragma unroll
            for (int mi = 0; mi < 4; mi++) {
                int m = wm * 64 + mi * 16 + g;
                afr[mi][0] = __float_as_uint(As[m * 44 + kb + tg]);
                afr[mi][1] = __float_as_uint(As[(m + 8) * 44 + kb + tg]);
                afr[mi][2] = __float_as_uint(As[m * 44 + kb + tg + 4]);
                afr[mi][3] = __float_as_uint(As[(m + 8) * 44 + kb + tg + 4]);
            }
            uint32_t bfr[5][2];
#pragma unroll
            for (int nj = 0; nj < 5; nj++) {
                int n = wn * 40 + nj * 8 + g;
                bfr[nj][0] = __float_as_uint(Bs[n * 44 + kb + tg]);
                bfr[nj][1] = __float_as_uint(Bs[n * 44 + kb + tg + 4]);
            }
#pragma unroll
            for (int mi = 0; mi < 4; mi++)
#pragma unroll
                for (int nj = 0; nj < 5; nj++)
                    mma_tf32(acc[mi][nj], afr[mi], bfr[nj]);
        }
    }
#undef STAGE

#pragma unroll
    for (int mi = 0; mi < 4; mi++) {
        int mrow = m0 + wm * 64 + mi * 16 + g;
#pragma unroll
        for (int nj = 0; nj < 5; nj++) {
            int ncol = n0 + wn * 40 + nj * 8 + 2 * tg;
            float bx = bc[ncol], by = bc[ncol + 1];
            *(float2*)(d_g + (size_t)mrow * G16 + ncol) =
                make_float2(acc[mi][nj][0] + bx, acc[mi][nj][1] + by);
            *(float2*)(d_g + (size_t)(mrow + 8) * G16 + ncol) =
                make_float2(acc[mi][nj][2] + bx, acc[mi][nj][3] + by);
        }
    }
}

// ---------------- init: zero h, reset barriers, build transposed mask --------
__global__ void init_misc(const int* __restrict__ masks) {
    int i = blockIdx.x * blockDim.x + threadIdx.x;
    if (i < 2 * 2 * Hh * Bsz) ((float*)d_h)[i] = 0.f;
    if (i < Tt * Bsz) {
        int t = i / Bsz, b = i % Bsz;
        d_mt[i] = (masks[b * Tt + t] == 0) ? 1.f : 0.f;
    }
    if (i < 2) d_barc[i] = 0;
}

// ---------------- persistent tensor-core bidirectional LSTM ----------------
// 2 dirs x 25 blocks; block owns 8 hidden units (N=32 gate rows), M=128 batch.
#define NDIRBLK 25

__global__ __launch_bounds__(256, 1)
void lstm_layer(const float* __restrict__ Whhf, const float* __restrict__ Whhb, int layer) {
    extern __shared__ float sm[];
    float* hs  = sm;            // [200][136]  = 27200 floats
    float* Wp  = sm + 27200;    // [32][206]   = 6592
    float* msk = sm + 33792;    // [128]

    const int tid = threadIdx.x;
    const int dir = blockIdx.x / NDIRBLK;
    const int u0  = (blockIdx.x % NDIRBLK) * 8;
    const float* Whh = dir ? Whhb : Whhf;
    float* out = layer ? d_rnn : d_x1;
    float* hbuf0 = d_h[dir][0];
    float* hbuf1 = d_h[dir][1];

    // pack W_hh slice, tf32, pair-packed for float2 B-fragment loads:
    // Wp[n][k0*8 + tg*2 + c] = W[grow][k0*8 + tg + 4c],  n = gate*8 + uu
    for (int i = tid; i < 32 * 200; i += 256) {
        int n = i / 200, p = i % 200;
        int k0 = p >> 3, r = p & 7, tg2 = r >> 1, c = r & 1;
        int k = k0 * 8 + tg2 + 4 * c;
        int grow = (n >> 3) * Hh + u0 + (n & 7);
        Wp[n * 206 + p] = to_tf32(Whh[(size_t)grow * Hh + k]);
    }

    const int lane = tid & 31;
    const int m0 = (tid >> 5) * 16;       // 8 warps, m-tile 16
    const int g = lane >> 2, tg = lane & 3;

    float cst[4] = {0.f, 0.f, 0.f, 0.f};
    float hreg[4] = {0.f, 0.f, 0.f, 0.f};
    volatile unsigned* barc = &d_barc[dir];

    __syncthreads();

    for (int s = 0; s < Tt; s++) {
        const int t = dir ? (Tt - 1 - s) : s;
        const float* hcur = (s & 1) ? hbuf1 : hbuf0;
        float* hnxt = (s & 1) ? hbuf0 : hbuf1;

        // stage full h_prev [200][128] -> smem [200][136], L1-bypassed
        for (int i = tid; i < 6400; i += 256) {
            int k = i >> 5, b4 = (i & 31) << 2;
            float4 v = __ldcg((const float4*)&hcur[k * 128 + b4]);
            *(float4*)&hs[k * 136 + b4] = v;
        }
        if (tid < 128) msk[tid] = d_mt[t * 128 + tid];

        // prefetch x-projection gates for this thread's C fragment
        float2 gx[4][2];
#pragma unroll
        for (int j = 0; j < 4; j++)
#pragma unroll
            for (int rh = 0; rh < 2; rh++) {
                int b = m0 + g + 8 * rh;
                gx[j][rh] = *(const float2*)&d_g[(size_t)(b * Tt + t) * G16 +
                                                 dir * 800 + j * 200 + u0 + 2 * tg];
            }

        __syncthreads();

        float acc[4][4];
#pragma unroll
        for (int j = 0; j < 4; j++)
#pragma unroll
            for (int r = 0; r < 4; r++) acc[j][r] = 0.f;

#pragma unroll
        for (int ik = 0; ik < 25; ik++) {
            const int kb = ik * 8;
            uint32_t a[4];
            a[0] = __float_as_uint(hs[(kb + tg) * 136 + m0 + g]);
            a[1] = __float_as_uint(hs[(kb + tg) * 136 + m0 + g + 8]);
            a[2] = __float_as_uint(hs[(kb + tg + 4) * 136 + m0 + g]);
            a[3] = __float_as_uint(hs[(kb + tg + 4) * 136 + m0 + g + 8]);
#pragma unroll
            for (int j = 0; j < 4; j++) {
                float2 bp = *(const float2*)&Wp[(j * 8 + g) * 206 + kb + tg * 2];
                uint32_t bb[2] = { __float_as_uint(bp.x), __float_as_uint(bp.y) };
                mma_tf32(acc[j], a, bb);
            }
        }

#pragma unroll
        for (int j = 0; j < 4; j++) {
            acc[j][0] += gx[j][0].x; acc[j][1] += gx[j][0].y;
            acc[j][2] += gx[j][1].x; acc[j][3] += gx[j][1].y;
        }

        // cell update fully in registers
#pragma unroll
        for (int r = 0; r < 4; r++) {
            int b  = m0 + g + 8 * (r >> 1);
            int uu = 2 * tg + (r & 1);
            float iv = sig_(acc[0][r]);
            float fv = sig_(acc[1][r]);
            float gv = tanh_(acc[2][r]);
            float ov = sig_(acc[3][r]);
            float m  = msk[b];
            float cn = fv * cst[r] + iv * gv;
            float hn = ov * tanh_(cn);
            float hnew = m * hn + (1.f - m) * hreg[r];
            cst[r] = m * cn + (1.f - m) * cst[r];
            hreg[r] = hnew;
            hnxt[(u0 + uu) * 128 + b] = to_tf32(hnew);
            float ho = m * hn;
            out[(size_t)(b * Tt + t) * IN1 + dir * Hh + u0 + uu] = layer ? ho : to_tf32(ho);
            if (layer && s == Tt - 1) d_hfin[dir][b * Hh + u0 + uu] = hnew;
        }

        // per-direction grid barrier
        __threadfence();
        __syncthreads();
        if (tid == 0) {
            atomicAdd((unsigned*)barc, 1u);
            unsigned tgt = (unsigned)NDIRBLK * (s + 1);
            while (*barc < tgt) {}
        }
        __syncthreads();
    }
}

// ---------------- span sums + queries ----------------
__global__ void span_kernel(const int* __restrict__ masks, const int* __restrict__ subj,
                            const int* __restrict__ obj) {
    int b = blockIdx.x;
    __shared__ float ssel[Tt];
    __shared__ float osel[Tt];
    for (int t = threadIdx.x; t < Tt; t += blockDim.x) {
        int m = masks[b * Tt + t];
        ssel[t] = (subj[b * Tt + t] + m == 0) ? 1.f : 0.f;
        osel[t] = (obj[b * Tt + t] + m == 0) ? 1.f : 0.f;
    }
    __syncthreads();
    for (int f = threadIdx.x; f < IN1; f += blockDim.x) {
        float ss = 0.f, os = 0.f;
        for (int t = 0; t < Tt; t++) {
            float v = d_rnn[(size_t)(b * Tt + t) * IN1 + f];
            ss += v * ssel[t];
            os += v * osel[t];
        }
        d_q[0][b * IN1 + f] = os;
        d_q[1][b * IN1 + f] = ss;
        d_q[2][b * IN1 + f] = (f < Hh) ? d_hfin[1][b * Hh + f]
                                       : d_hfin[0][b * Hh + f - Hh];
    }
}

// ---------------- attention pooling ----------------
__global__ void attn_kernel(const int* __restrict__ masks) {
    int b = blockIdx.x / 3, qi = blockIdx.x % 3;
    __shared__ float qv[IN1];
    __shared__ float ps[Tt];
    __shared__ float red[256];
    int tid = threadIdx.x;
    for (int f = tid; f < IN1; f += 256) qv[f] = d_q[qi][b * IN1 + f];
    __syncthreads();

    const float* row = d_rnn + (size_t)(b * Tt + tid) * IN1;
    float sc = 0.f;
    for (int k = 0; k < IN1; k++) sc += qv[k] * row[k];
    sc *= 0.05f;
    if (masks[b * Tt + tid] != 0) sc = -1e9f;

    red[tid] = sc; __syncthreads();
    for (int o = 128; o; o >>= 1) { if (tid < o) red[tid] = fmaxf(red[tid], red[tid + o]); __syncthreads(); }
    float mx = red[0]; __syncthreads();
    float e = __expf(sc - mx);
    red[tid] = e; __syncthreads();
    for (int o = 128; o; o >>= 1) { if (tid < o) red[tid] += red[tid + o]; __syncthreads(); }
    float inv = 1.f / red[0];
    ps[tid] = e * inv;
    __syncthreads();

    for (int f = tid; f < IN1; f += 256) {
        float a = 0.f;
        for (int t = 0; t < Tt; t++) a += ps[t] * d_rnn[(size_t)(b * Tt + t) * IN1 + f];
        d_att[qi][b * IN1 + f] = a;
    }
}

// ---------------- final MLP head ----------------
__global__ void final_kernel(const float* __restrict__ wo_w, const float* __restrict__ wo_b,
                             const float* __restrict__ ws_w, const float* __restrict__ ws_b,
                             const float* __restrict__ wg_w, const float* __restrict__ wg_b,
                             const float* __restrict__ cls_w, const float* __restrict__ cls_b,
                             float* __restrict__ outp) {
    int b = blockIdx.x;
    __shared__ float hv[Hh];
    int j = threadIdx.x;
    if (j < Hh) {
        float a = wo_b[j] + ws_b[j] + wg_b[j];
        const float* o = &d_att[0][b * IN1];
        const float* s = &d_att[1][b * IN1];
        const float* gq = &d_att[2][b * IN1];
        const float* wo = wo_w + (size_t)j * IN1;
        const float* ws = ws_w + (size_t)j * IN1;
        const float* wg = wg_w + (size_t)j * IN1;
        for (int k = 0; k < IN1; k++)
            a += o[k] * wo[k] + s[k] * ws[k] + gq[k] * wg[k];
        hv[j] = fmaxf(a, 0.f);
    }
    __syncthreads();
    if (j < 64) {
        int n = j >> 5, lane = j & 31;
        float p = 0.f;
        for (int k = lane; k < Hh; k += 32) p += hv[k] * cls_w[n * Hh + k];
        for (int o = 16; o; o >>= 1) p += __shfl_down_sync(0xffffffffu, p, o);
        if (lane == 0) outp[b * NCLASS + n] = p + cls_b[n];
    }
}

// ---------------- launcher ----------------
extern "C" void kernel_launch(void* const* d_in, const int* in_sizes, int n_in,
                              void* d_out, int out_size) {
    const int*   words    = (const int*)d_in[0];
    const int*   masks    = (const int*)d_in[1];
    const int*   pos      = (const int*)d_in[2];
    const int*   ner      = (const int*)d_in[3];
    const int*   subj_pos = (const int*)d_in[4];
    const int*   obj_pos  = (const int*)d_in[5];
    const float* emb_w    = (const float*)d_in[6];
    const float* pos_w    = (const float*)d_in[7];
    const float* ner_w    = (const float*)d_in[8];
    const float* w_ih_l0f = (const float*)d_in[9];
    const float* w_hh_l0f = (const float*)d_in[10];
    const float* b_l0f    = (const float*)d_in[11];
    const float* w_ih_l0b = (const float*)d_in[12];
    const float* w_hh_l0b = (const float*)d_in[13];
    const float* b_l0b    = (const float*)d_in[14];
    const float* w_ih_l1f = (const float*)d_in[15];
    const float* w_hh_l1f = (const float*)d_in[16];
    const float* b_l1f    = (const float*)d_in[17];
    const float* w_ih_l1b = (const float*)d_in[18];
    const float* w_hh_l1b = (const float*)d_in[19];
    const float* b_l1b    = (const float*)d_in[20];
    const float* wo_w     = (const float*)d_in[21];
    const float* wo_b     = (const float*)d_in[22];
    const float* ws_w     = (const float*)d_in[23];
    const float* ws_b     = (const float*)d_in[24];
    const float* wg_w     = (const float*)d_in[25];
    const float* wg_b     = (const float*)d_in[26];
    const float* cls_w    = (const float*)d_in[27];
    const float* cls_b    = (const float*)d_in[28];

    static const int GEMM_SMEM = 25344 * 4;   // 101376 B
    static const int LSTM_SMEM = 33920 * 4;   // 135680 B
    cudaFuncSetAttribute(gemm_tf32, cudaFuncAttributeMaxDynamicSharedMemorySize, GEMM_SMEM);
    cudaFuncSetAttribute(lstm_layer, cudaFuncAttributeMaxDynamicSharedMemorySize, LSTM_SMEM);

    dim3 ggrid(10, 256);   // N=1600/160, M=32768/128
    int wpgrid = (G16 * 400 + 255) / 256;
    int imgrid = (2 * 2 * Hh * Bsz + 255) / 256;

    // launch order puts lstm_layer at index 5 for ncu (-s 5 -c 1)
    embed_kernel<<<(BT * 400 + 255) / 256, 256>>>(words, pos, ner, emb_w, pos_w, ner_w); // 0
    wprep_kernel<<<wpgrid, 256>>>(w_ih_l0f, w_ih_l0b, b_l0f, b_l0b, 360, 0);             // 1
    wprep_kernel<<<wpgrid, 256>>>(w_ih_l1f, w_ih_l1b, b_l1f, b_l1b, 400, 1);             // 2
    gemm_tf32<<<ggrid, 256, GEMM_SMEM>>>(0, 0);                                           // 3
    init_misc<<<imgrid, 256>>>(masks);                                                    // 4
    lstm_layer<<<2 * NDIRBLK, 256, LSTM_SMEM>>>(w_hh_l0f, w_hh_l0b, 0);                   // 5 <- ncu
    gemm_tf32<<<ggrid, 256, GEMM_SMEM>>>(1, 1);                                           // 6
    init_misc<<<imgrid, 256>>>(masks);                                                    // 7
    lstm_layer<<<2 * NDIRBLK, 256, LSTM_SMEM>>>(w_hh_l1f, w_hh_l1b, 1);                   // 8
    span_kernel<<<Bsz, 256>>>(masks, subj_pos, obj_pos);                                  // 9
    attn_kernel<<<Bsz * 3, 256>>>(masks);                                                 // 10
    final_kernel<<<Bsz, 256>>>(wo_w, wo_b, ws_w, ws_b, wg_w, wg_b, cls_w, cls_b,
                               (float*)d_out);                                            // 11
}

// round 4
// speedup vs baseline: 2.5626x; 1.1421x over previous
#include <cuda_runtime.h>
#include <cstdint>

#define Bsz 128
#define Tt 256
#define Hh 200
#define IN1 400
#define BT (Bsz*Tt)
#define NCLASS 2
#define G16 1600

// ---------------- device scratch (static, no allocation) ----------------
__device__ __align__(16) float d_x0[BT*400];        // embeddings, tf32, K-padded to 400
__device__ __align__(16) float d_x1[BT*400];        // layer0 output (tf32)
__device__ __align__(16) float d_rnn[BT*400];       // layer1 output (fp32)
__device__ __align__(16) float d_g[(size_t)BT*G16]; // gates: [bt][fwd 800 | bwd 800]
__device__ __align__(16) float d_h[2][2][Bsz*Hh];   // [dir][buf][b*200 + u]
__device__ __align__(16) float d_hfin[2][Bsz*Hh];
__device__ __align__(16) float d_q[3][Bsz*IN1];
__device__ __align__(16) float d_att[3][Bsz*IN1];
__device__ __align__(16) float d_wcat[2][G16*400];  // padded tf32 W_ih per layer
__device__ __align__(16) float d_bcat[2][G16];
__device__ __align__(16) float d_mt[Tt*Bsz];        // keep-mask transposed [t][b]
__device__ unsigned d_barc2[2*8*32];                // per (dir,warp) counters, 128B apart

// ---------------- helpers ----------------
__device__ __forceinline__ float sig_(float x) { return 1.f / (1.f + __expf(-x)); }
__device__ __forceinline__ float tanh_(float x) {
    float xc = fminf(fmaxf(x, -15.f), 15.f);
    float e = __expf(2.f * xc);
    return (e - 1.f) / (e + 1.f);
}
__device__ __forceinline__ float to_tf32(float x) {
    float r;
    asm("cvt.rna.tf32.f32 %0, %1;" : "=f"(r) : "f"(x));
    return r;
}
__device__ __forceinline__ void mma_tf32(float* d, const uint32_t* a, const uint32_t* b) {
    asm volatile(
        "mma.sync.aligned.m16n8k8.row.col.f32.tf32.tf32.f32 "
        "{%0,%1,%2,%3}, {%4,%5,%6,%7}, {%8,%9}, {%0,%1,%2,%3};"
        : "+f"(d[0]), "+f"(d[1]), "+f"(d[2]), "+f"(d[3])
        : "r"(a[0]), "r"(a[1]), "r"(a[2]), "r"(a[3]), "r"(b[0]), "r"(b[1]));
}
__device__ __forceinline__ void cp16(uint32_t saddr, const void* gaddr) {
    asm volatile("cp.async.cg.shared.global [%0], [%1], 16;" :: "r"(saddr), "l"(gaddr));
}
__device__ __forceinline__ unsigned ld_acq(const unsigned* p) {
    unsigned v;
    asm volatile("ld.acquire.gpu.global.u32 %0, [%1];" : "=r"(v) : "l"(p) : "memory");
    return v;
}
__device__ __forceinline__ void red_rel(unsigned* p) {
    asm volatile("red.release.gpu.global.add.u32 [%0], %1;" :: "l"(p), "r"(1u) : "memory");
}

// ---------------- embedding concat (tf32-rounded, K padded to 400) ---------
__global__ void embed_kernel(const int* __restrict__ words, const int* __restrict__ pos,
                             const int* __restrict__ ner,
                             const float* __restrict__ emb_w, const float* __restrict__ pos_w,
                             const float* __restrict__ ner_w) {
    int idx = blockIdx.x * blockDim.x + threadIdx.x;
    if (idx >= BT * 400) return;
    int c = idx % 400, bt = idx / 400;
    float v = 0.f;
    if (c < 300)        v = emb_w[(size_t)words[bt] * 300 + c];
    else if (c < 330)   v = pos_w[(size_t)pos[bt] * 30 + (c - 300)];
    else if (c < 360)   v = ner_w[(size_t)ner[bt] * 30 + (c - 330)];
    d_x0[idx] = to_tf32(v);
}

// ---------------- W_ih prep: concat fwd+bwd, pad K to 400, tf32 ------------
__global__ void wprep_kernel(const float* __restrict__ wf, const float* __restrict__ wb,
                             const float* __restrict__ bf, const float* __restrict__ bb_,
                             int K, int layer) {
    int i = blockIdx.x * blockDim.x + threadIdx.x;
    if (i < G16 * 400) {
        int n = i / 400, k = i % 400;
        float v = 0.f;
        if (k < K) {
            const float* W = (n < 800) ? wf : wb;
            int nn = (n < 800) ? n : n - 800;
            v = to_tf32(W[(size_t)nn * K + k]);
        }
        d_wcat[layer][i] = v;
    }
    if (i < G16) d_bcat[layer][i] = (i < 800) ? bf[i] : bb_[i - 800];
}

// ---------------- TF32 GEMM: d_g[32768,1600] = A[32768,400] @ Wcat^T + bias -
// BM=128, BN=160, BK=40, cp.async double-buffer, 512 thr (16 warps, 4x4),
// warp tile 32x40 -> acc[2][5][4].
__global__ __launch_bounds__(512, 1)
void gemm_tf32(int asel, int layer) {
    extern __shared__ float smg[];
    float* Abuf[2] = { smg, smg + 5632 };              // 128*44 each
    float* Bbuf[2] = { smg + 11264, smg + 18304 };     // 160*44 each
    const float* A = asel ? d_x1 : d_x0;
    const float* Wc = d_wcat[layer];
    const float* bc = d_bcat[layer];

    const int tid = threadIdx.x;
    const int lane = tid & 31, w = tid >> 5;
    const int wm = w & 3, wn = w >> 2;
    const int g = lane >> 2, tg = lane & 3;
    const int m0 = blockIdx.y * 128, n0 = blockIdx.x * 160;

    uint32_t sA[2], sB[2];
    sA[0] = (uint32_t)__cvta_generic_to_shared(Abuf[0]);
    sA[1] = (uint32_t)__cvta_generic_to_shared(Abuf[1]);
    sB[0] = (uint32_t)__cvta_generic_to_shared(Bbuf[0]);
    sB[1] = (uint32_t)__cvta_generic_to_shared(Bbuf[1]);

    float acc[2][5][4];
#pragma unroll
    for (int i = 0; i < 2; i++)
#pragma unroll
        for (int j = 0; j < 5; j++)
#pragma unroll
            for (int r = 0; r < 4; r++) acc[i][j][r] = 0.f;

#define STAGE(IT, BUF) do {                                                    \
        int k0 = (IT) * 40;                                                    \
        for (int i = tid; i < 1280; i += 512) {                                \
            int row = i / 10, c4 = (i % 10) * 4;                               \
            cp16(sA[BUF] + (uint32_t)(row * 44 + c4) * 4,                      \
                 A + (size_t)(m0 + row) * 400 + k0 + c4);                      \
        }                                                                      \
        for (int i = tid; i < 1600; i += 512) {                                \
            int row = i / 10, c4 = (i % 10) * 4;                               \
            cp16(sB[BUF] + (uint32_t)(row * 44 + c4) * 4,                      \
                 Wc + (size_t)(n0 + row) * 400 + k0 + c4);                     \
        }                                                                      \
        asm volatile("cp.async.commit_group;");                                \
    } while (0)

    STAGE(0, 0);

    for (int it = 0; it < 10; it++) {
        const int cur = it & 1;
        asm volatile("cp.async.wait_group 0;");
        __syncthreads();
        if (it < 9) STAGE(it + 1, cur ^ 1);

        const float* As = Abuf[cur];
        const float* Bs = Bbuf[cur];
#pragma unroll
        for (int ks = 0; ks < 5; ks++) {
            const int kb = ks * 8;
            uint32_t afr[2][4];
#pragma unroll
            for (int mi = 0; mi < 2; mi++) {
                int m = wm * 32 + mi * 16 + g;
                afr[mi][0] = __float_as_uint(As[m * 44 + kb + tg]);
                afr[mi][1] = __float_as_uint(As[(m + 8) * 44 + kb + tg]);
                afr[mi][2] = __float_as_uint(As[m * 44 + kb + tg + 4]);
                afr[mi][3] = __float_as_uint(As[(m + 8) * 44 + kb + tg + 4]);
            }
            uint32_t bfr[5][2];
#pragma unroll
            for (int nj = 0; nj < 5; nj++) {
                int n = wn * 40 + nj * 8 + g;
                bfr[nj][0] = __float_as_uint(Bs[n * 44 + kb + tg]);
                bfr[nj][1] = __float_as_uint(Bs[n * 44 + kb + tg + 4]);
            }
#pragma unroll
            for (int mi = 0; mi < 2; mi++)
#pragma unroll
                for (int nj = 0; nj < 5; nj++)
                    mma_tf32(acc[mi][nj], afr[mi], bfr[nj]);
        }
    }
#undef STAGE

#pragma unroll
    for (int mi = 0; mi < 2; mi++) {
        int mrow = m0 + wm * 32 + mi * 16 + g;
#pragma unroll
        for (int nj = 0; nj < 5; nj++) {
            int ncol = n0 + wn * 40 + nj * 8 + 2 * tg;
            float bx = bc[ncol], by = bc[ncol + 1];
            *(float2*)(d_g + (size_t)mrow * G16 + ncol) =
                make_float2(acc[mi][nj][0] + bx, acc[mi][nj][1] + by);
            *(float2*)(d_g + (size_t)(mrow + 8) * G16 + ncol) =
                make_float2(acc[mi][nj][2] + bx, acc[mi][nj][3] + by);
        }
    }
}

// ---------------- init: zero h, reset barriers, build transposed mask ------
__global__ void init_misc(const int* __restrict__ masks) {
    int i = blockIdx.x * blockDim.x + threadIdx.x;
    if (i < 2 * 2 * Bsz * Hh) ((float*)d_h)[i] = 0.f;
    if (i < Tt * Bsz) {
        int t = i / Bsz, b = i % Bsz;
        d_mt[i] = (masks[b * Tt + t] == 0) ? 1.f : 0.f;
    }
    if (i < 2 * 8 * 32) d_barc2[i] = 0;
}

// ---------------- persistent tensor-core bidirectional LSTM ----------------
// 2 dirs x 25 blocks; block owns 8 hidden units; warp w owns batch rows
// [16w,16w+16) -> 8 independent cross-block warp-groups, no __syncthreads
// in the step loop.
#define NDIRBLK 25

__global__ __launch_bounds__(256, 1)
void lstm_layer(const float* __restrict__ Whhf, const float* __restrict__ Whhb, int layer) {
    extern __shared__ float sm[];
    float* hs = sm;            // [128][212] = 27136 floats
    float* Wp = sm + 27136;    // [32][206]  = 6592 floats

    const int tid = threadIdx.x;
    const int lane = tid & 31, w = tid >> 5;
    const int dir = blockIdx.x / NDIRBLK;
    const int u0  = (blockIdx.x % NDIRBLK) * 8;
    const float* Whh = dir ? Whhb : Whhf;
    float* out = layer ? d_rnn : d_x1;
    float* hbuf0 = d_h[dir][0];
    float* hbuf1 = d_h[dir][1];

    // pack W_hh slice, tf32, pair-packed for float2 B-fragment loads:
    // Wp[n][k0*8 + tg*2 + c] = W[grow][k0*8 + tg + 4c],  n = gate*8 + uu
    for (int i = tid; i < 32 * 200; i += 256) {
        int n = i / 200, p = i % 200;
        int k0 = p >> 3, r = p & 7, tg2 = r >> 1, c = r & 1;
        int k = k0 * 8 + tg2 + 4 * c;
        int grow = (n >> 3) * Hh + u0 + (n & 7);
        Wp[n * 206 + p] = to_tf32(Whh[(size_t)grow * Hh + k]);
    }
    __syncthreads();

    const int m0 = w * 16;
    const int g = lane >> 2, tg = lane & 3;
    unsigned* bar = &d_barc2[((dir << 3) + w) * 32];
    const uint32_t hs_base = (uint32_t)__cvta_generic_to_shared(hs);

    float cst[4] = {0.f, 0.f, 0.f, 0.f};
    float hreg[4] = {0.f, 0.f, 0.f, 0.f};

    // prefetch gates + mask for step 0
    float2 gx[4][2];
    float mk0, mk1;
    {
        int t0 = dir ? Tt - 1 : 0;
#pragma unroll
        for (int j = 0; j < 4; j++) {
            gx[j][0] = *(const float2*)&d_g[(size_t)((m0 + g) * Tt + t0) * G16 +
                                            dir * 800 + j * 200 + u0 + 2 * tg];
            gx[j][1] = *(const float2*)&d_g[(size_t)((m0 + g + 8) * Tt + t0) * G16 +
                                            dir * 800 + j * 200 + u0 + 2 * tg];
        }
        mk0 = d_mt[t0 * Bsz + m0 + g];
        mk1 = d_mt[t0 * Bsz + m0 + g + 8];
    }

    for (int s = 0; s < Tt; s++) {
        const int t = dir ? (Tt - 1 - s) : s;
        const float* hcur = (s & 1) ? hbuf1 : hbuf0;
        float* hnxt = (s & 1) ? hbuf0 : hbuf1;

        // wait for all 25 blocks of this warp-group to finish step s-1
        if (s && lane == 0) {
            unsigned tgt = 800u * (unsigned)s;   // 25 blocks * 32 lanes per step
            while (ld_acq(bar) < tgt) {}
        }
        __syncwarp();

        // stage this warp's 16 batch rows of h_prev (L1-bypassed)
        for (int i = lane; i < 800; i += 32) {
            int r16 = i / 50, c4 = (i % 50) * 4;
            cp16(hs_base + (uint32_t)((m0 + r16) * 212 + c4) * 4,
                 hcur + (size_t)(m0 + r16) * Hh + c4);
        }
        asm volatile("cp.async.commit_group;");
        asm volatile("cp.async.wait_group 0;");
        __syncwarp();

        float acc[4][4];
#pragma unroll
        for (int j = 0; j < 4; j++)
#pragma unroll
            for (int r = 0; r < 4; r++) acc[j][r] = 0.f;

#pragma unroll
        for (int ik = 0; ik < 25; ik++) {
            const int kb = ik * 8;
            uint32_t a[4];
            a[0] = __float_as_uint(hs[(m0 + g) * 212 + kb + tg]);
            a[1] = __float_as_uint(hs[(m0 + g + 8) * 212 + kb + tg]);
            a[2] = __float_as_uint(hs[(m0 + g) * 212 + kb + tg + 4]);
            a[3] = __float_as_uint(hs[(m0 + g + 8) * 212 + kb + tg + 4]);
#pragma unroll
            for (int j = 0; j < 4; j++) {
                float2 bp = *(const float2*)&Wp[(j * 8 + g) * 206 + kb + tg * 2];
                uint32_t bb[2] = { __float_as_uint(bp.x), __float_as_uint(bp.y) };
                mma_tf32(acc[j], a, bb);
            }
        }

#pragma unroll
        for (int j = 0; j < 4; j++) {
            acc[j][0] += gx[j][0].x; acc[j][1] += gx[j][0].y;
            acc[j][2] += gx[j][1].x; acc[j][3] += gx[j][1].y;
        }

        // cell update in registers
        float ho[4];
#pragma unroll
        for (int r = 0; r < 4; r++) {
            float m = (r >> 1) ? mk1 : mk0;
            float iv = sig_(acc[0][r]);
            float fv = sig_(acc[1][r]);
            float gv = tanh_(acc[2][r]);
            float ov = sig_(acc[3][r]);
            float cn = fv * cst[r] + iv * gv;
            float hn = ov * tanh_(cn);
            float hnew = m * hn + (1.f - m) * hreg[r];
            cst[r] = m * cn + (1.f - m) * cst[r];
            hreg[r] = hnew;
            ho[r] = m * hn;
        }

        // store h_next (tf32, paired)
        *(float2*)&hnxt[(size_t)(m0 + g) * Hh + u0 + 2 * tg] =
            make_float2(to_tf32(hreg[0]), to_tf32(hreg[1]));
        *(float2*)&hnxt[(size_t)(m0 + g + 8) * Hh + u0 + 2 * tg] =
            make_float2(to_tf32(hreg[2]), to_tf32(hreg[3]));

        __syncwarp();
        red_rel(bar);   // every lane: releases its own h stores

        // ---- tail (not on other blocks' critical path) ----
        {
            float2 o0, o1;
            if (layer) { o0 = make_float2(ho[0], ho[1]); o1 = make_float2(ho[2], ho[3]); }
            else { o0 = make_float2(to_tf32(ho[0]), to_tf32(ho[1]));
                   o1 = make_float2(to_tf32(ho[2]), to_tf32(ho[3])); }
            *(float2*)&out[(size_t)((m0 + g) * Tt + t) * IN1 + dir * Hh + u0 + 2 * tg] = o0;
            *(float2*)&out[(size_t)((m0 + g + 8) * Tt + t) * IN1 + dir * Hh + u0 + 2 * tg] = o1;
        }
        if (layer && s == Tt - 1) {
            *(float2*)&d_hfin[dir][(m0 + g) * Hh + u0 + 2 * tg] =
                make_float2(hreg[0], hreg[1]);
            *(float2*)&d_hfin[dir][(m0 + g + 8) * Hh + u0 + 2 * tg] =
                make_float2(hreg[2], hreg[3]);
        }
        if (s < Tt - 1) {
            int tn = dir ? (Tt - 2 - s) : (s + 1);
#pragma unroll
            for (int j = 0; j < 4; j++) {
                gx[j][0] = *(const float2*)&d_g[(size_t)((m0 + g) * Tt + tn) * G16 +
                                                dir * 800 + j * 200 + u0 + 2 * tg];
                gx[j][1] = *(const float2*)&d_g[(size_t)((m0 + g + 8) * Tt + tn) * G16 +
                                                dir * 800 + j * 200 + u0 + 2 * tg];
            }
            mk0 = d_mt[tn * Bsz + m0 + g];
            mk1 = d_mt[tn * Bsz + m0 + g + 8];
        }
    }
}

// ---------------- span sums + queries ----------------
__global__ void span_kernel(const int* __restrict__ masks, const int* __restrict__ subj,
                            const int* __restrict__ obj) {
    int b = blockIdx.x;
    __shared__ float ssel[Tt];
    __shared__ float osel[Tt];
    for (int t = threadIdx.x; t < Tt; t += blockDim.x) {
        int m = masks[b * Tt + t];
        ssel[t] = (subj[b * Tt + t] + m == 0) ? 1.f : 0.f;
        osel[t] = (obj[b * Tt + t] + m == 0) ? 1.f : 0.f;
    }
    __syncthreads();
    for (int f = threadIdx.x; f < IN1; f += blockDim.x) {
        float ss = 0.f, os = 0.f;
        for (int t = 0; t < Tt; t++) {
            float v = d_rnn[(size_t)(b * Tt + t) * IN1 + f];
            ss += v * ssel[t];
            os += v * osel[t];
        }
        d_q[0][b * IN1 + f] = os;
        d_q[1][b * IN1 + f] = ss;
        d_q[2][b * IN1 + f] = (f < Hh) ? d_hfin[1][b * Hh + f]
                                       : d_hfin[0][b * Hh + f - Hh];
    }
}

// ---------------- attention pooling ----------------
__global__ void attn_kernel(const int* __restrict__ masks) {
    int b = blockIdx.x / 3, qi = blockIdx.x % 3;
    __shared__ float qv[IN1];
    __shared__ float ps[Tt];
    __shared__ float red[256];
    int tid = threadIdx.x;
    for (int f = tid; f < IN1; f += 256) qv[f] = d_q[qi][b * IN1 + f];
    __syncthreads();

    const float* row = d_rnn + (size_t)(b * Tt + tid) * IN1;
    float sc = 0.f;
    for (int k = 0; k < IN1; k++) sc += qv[k] * row[k];
    sc *= 0.05f;
    if (masks[b * Tt + tid] != 0) sc = -1e9f;

    red[tid] = sc; __syncthreads();
    for (int o = 128; o; o >>= 1) { if (tid < o) red[tid] = fmaxf(red[tid], red[tid + o]); __syncthreads(); }
    float mx = red[0]; __syncthreads();
    float e = __expf(sc - mx);
    red[tid] = e; __syncthreads();
    for (int o = 128; o; o >>= 1) { if (tid < o) red[tid] += red[tid + o]; __syncthreads(); }
    float inv = 1.f / red[0];
    ps[tid] = e * inv;
    __syncthreads();

    for (int f = tid; f < IN1; f += 256) {
        float a = 0.f;
        for (int t = 0; t < Tt; t++) a += ps[t] * d_rnn[(size_t)(b * Tt + t) * IN1 + f];
        d_att[qi][b * IN1 + f] = a;
    }
}

// ---------------- final MLP head ----------------
__global__ void final_kernel(const float* __restrict__ wo_w, const float* __restrict__ wo_b,
                             const float* __restrict__ ws_w, const float* __restrict__ ws_b,
                             const float* __restrict__ wg_w, const float* __restrict__ wg_b,
                             const float* __restrict__ cls_w, const float* __restrict__ cls_b,
                             float* __restrict__ outp) {
    int b = blockIdx.x;
    __shared__ float hv[Hh];
    int j = threadIdx.x;
    if (j < Hh) {
        float a = wo_b[j] + ws_b[j] + wg_b[j];
        const float* o = &d_att[0][b * IN1];
        const float* s = &d_att[1][b * IN1];
        const float* gq = &d_att[2][b * IN1];
        const float* wo = wo_w + (size_t)j * IN1;
        const float* ws = ws_w + (size_t)j * IN1;
        const float* wg = wg_w + (size_t)j * IN1;
        for (int k = 0; k < IN1; k++)
            a += o[k] * wo[k] + s[k] * ws[k] + gq[k] * wg[k];
        hv[j] = fmaxf(a, 0.f);
    }
    __syncthreads();
    if (j < 64) {
        int n = j >> 5, lane = j & 31;
        float p = 0.f;
        for (int k = lane; k < Hh; k += 32) p += hv[k] * cls_w[n * Hh + k];
        for (int o = 16; o; o >>= 1) p += __shfl_down_sync(0xffffffffu, p, o);
        if (lane == 0) outp[b * NCLASS + n] = p + cls_b[n];
    }
}

// ---------------- launcher ----------------
extern "C" void kernel_launch(void* const* d_in, const int* in_sizes, int n_in,
                              void* d_out, int out_size) {
    const int*   words    = (const int*)d_in[0];
    const int*   masks    = (const int*)d_in[1];
    const int*   pos      = (const int*)d_in[2];
    const int*   ner      = (const int*)d_in[3];
    const int*   subj_pos = (const int*)d_in[4];
    const int*   obj_pos  = (const int*)d_in[5];
    const float* emb_w    = (const float*)d_in[6];
    const float* pos_w    = (const float*)d_in[7];
    const float* ner_w    = (const float*)d_in[8];
    const float* w_ih_l0f = (const float*)d_in[9];
    const float* w_hh_l0f = (const float*)d_in[10];
    const float* b_l0f    = (const float*)d_in[11];
    const float* w_ih_l0b = (const float*)d_in[12];
    const float* w_hh_l0b = (const float*)d_in[13];
    const float* b_l0b    = (const float*)d_in[14];
    const float* w_ih_l1f = (const float*)d_in[15];
    const float* w_hh_l1f = (const float*)d_in[16];
    const float* b_l1f    = (const float*)d_in[17];
    const float* w_ih_l1b = (const float*)d_in[18];
    const float* w_hh_l1b = (const float*)d_in[19];
    const float* b_l1b    = (const float*)d_in[20];
    const float* wo_w     = (const float*)d_in[21];
    const float* wo_b     = (const float*)d_in[22];
    const float* ws_w     = (const float*)d_in[23];
    const float* ws_b     = (const float*)d_in[24];
    const float* wg_w     = (const float*)d_in[25];
    const float* wg_b     = (const float*)d_in[26];
    const float* cls_w    = (const float*)d_in[27];
    const float* cls_b    = (const float*)d_in[28];

    static const int GEMM_SMEM = 25344 * 4;   // 101376 B
    static const int LSTM_SMEM = 33728 * 4;   // 134912 B
    cudaFuncSetAttribute(gemm_tf32, cudaFuncAttributeMaxDynamicSharedMemorySize, GEMM_SMEM);
    cudaFuncSetAttribute(lstm_layer, cudaFuncAttributeMaxDynamicSharedMemorySize, LSTM_SMEM);

    dim3 ggrid(10, 256);   // N=1600/160, M=32768/128
    int wpgrid = (G16 * 400 + 255) / 256;
    int imgrid = (BT + 255) / 256;

    embed_kernel<<<(BT * 400 + 255) / 256, 256>>>(words, pos, ner, emb_w, pos_w, ner_w); // 0
    wprep_kernel<<<wpgrid, 256>>>(w_ih_l0f, w_ih_l0b, b_l0f, b_l0b, 360, 0);             // 1
    wprep_kernel<<<wpgrid, 256>>>(w_ih_l1f, w_ih_l1b, b_l1f, b_l1b, 400, 1);             // 2
    gemm_tf32<<<ggrid, 512, GEMM_SMEM>>>(0, 0);                                           // 3
    init_misc<<<imgrid, 256>>>(masks);                                                    // 4
    lstm_layer<<<2 * NDIRBLK, 256, LSTM_SMEM>>>(w_hh_l0f, w_hh_l0b, 0);                   // 5
    gemm_tf32<<<ggrid, 512, GEMM_SMEM>>>(1, 1);                                           // 6
    init_misc<<<imgrid, 256>>>(masks);                                                    // 7
    lstm_layer<<<2 * NDIRBLK, 256, LSTM_SMEM>>>(w_hh_l1f, w_hh_l1b, 1);                   // 8
    span_kernel<<<Bsz, 256>>>(masks, subj_pos, obj_pos);                                  // 9
    attn_kernel<<<Bsz * 3, 256>>>(masks);                                                 // 10
    final_kernel<<<Bsz, 256>>>(wo_w, wo_b, ws_w, ws_b, wg_w, wg_b, cls_w, cls_b,
                               (float*)d_out);                                            // 11
}

// round 5
// speedup vs baseline: 3.4148x; 1.3326x over previous
#include <cuda_runtime.h>
#include <cstdint>

#define Bsz 128
#define Tt 256
#define Hh 200
#define IN1 400
#define BT (Bsz*Tt)
#define NCLASS 2
#define G16 1600

// ---------------- device scratch (static, no allocation) ----------------
__device__ __align__(16) float d_x0[BT*400];        // embeddings, tf32, K-padded to 400
__device__ __align__(16) float d_x1[BT*400];        // layer0 output (tf32)
__device__ __align__(16) float d_rnn[BT*400];       // layer1 output (fp32)
__device__ __align__(16) float d_g[(size_t)BT*G16]; // gates: [bt][fwd 800 | bwd 800]
__device__ __align__(16) float d_h[2][2][Bsz*Hh];   // [dir][buf][b*200 + u]
__device__ __align__(16) float d_hfin[2][Bsz*Hh];
__device__ __align__(16) float d_q[3][Bsz*IN1];
__device__ __align__(16) float d_att[3][Bsz*IN1];
__device__ __align__(16) float d_wcat[2][G16*400];  // padded tf32 W_ih per layer
__device__ __align__(16) float d_bcat[2][G16];
__device__ __align__(16) float d_mt[Tt*Bsz];        // keep-mask transposed [t][b]
__device__ unsigned d_barc3[512];                   // 16 groups x 32 per-lane slots

// ---------------- helpers ----------------
__device__ __forceinline__ float sig_(float x) { return 1.f / (1.f + __expf(-x)); }
__device__ __forceinline__ float tanh_(float x) {
    float xc = fminf(fmaxf(x, -15.f), 15.f);
    float e = __expf(2.f * xc);
    return (e - 1.f) / (e + 1.f);
}
__device__ __forceinline__ float to_tf32(float x) {
    float r;
    asm("cvt.rna.tf32.f32 %0, %1;" : "=f"(r) : "f"(x));
    return r;
}
__device__ __forceinline__ void mma_tf32(float* d, const uint32_t* a, const uint32_t* b) {
    asm volatile(
        "mma.sync.aligned.m16n8k8.row.col.f32.tf32.tf32.f32 "
        "{%0,%1,%2,%3}, {%4,%5,%6,%7}, {%8,%9}, {%0,%1,%2,%3};"
        : "+f"(d[0]), "+f"(d[1]), "+f"(d[2]), "+f"(d[3])
        : "r"(a[0]), "r"(a[1]), "r"(a[2]), "r"(a[3]), "r"(b[0]), "r"(b[1]));
}
__device__ __forceinline__ void cp16(uint32_t saddr, const void* gaddr) {
    asm volatile("cp.async.cg.shared.global [%0], [%1], 16;" :: "r"(saddr), "l"(gaddr));
}
__device__ __forceinline__ unsigned ld_acq(const unsigned* p) {
    unsigned v;
    asm volatile("ld.acquire.gpu.global.u32 %0, [%1];" : "=r"(v) : "l"(p) : "memory");
    return v;
}
__device__ __forceinline__ void red_rel(unsigned* p) {
    asm volatile("red.release.gpu.global.add.u32 [%0], %1;" :: "l"(p), "r"(1u) : "memory");
}

// ---------------- embedding concat (tf32-rounded, K padded to 400) ---------
__global__ void embed_kernel(const int* __restrict__ words, const int* __restrict__ pos,
                             const int* __restrict__ ner,
                             const float* __restrict__ emb_w, const float* __restrict__ pos_w,
                             const float* __restrict__ ner_w) {
    int idx = blockIdx.x * blockDim.x + threadIdx.x;
    if (idx >= BT * 400) return;
    int c = idx % 400, bt = idx / 400;
    float v = 0.f;
    if (c < 300)        v = emb_w[(size_t)words[bt] * 300 + c];
    else if (c < 330)   v = pos_w[(size_t)pos[bt] * 30 + (c - 300)];
    else if (c < 360)   v = ner_w[(size_t)ner[bt] * 30 + (c - 330)];
    d_x0[idx] = to_tf32(v);
}

// ---------------- prep: both layers' W_ih concat + biases + mask + h/bar init
__global__ void prep_kernel(const float* __restrict__ wf0, const float* __restrict__ wb0,
                            const float* __restrict__ bf0, const float* __restrict__ bb0,
                            const float* __restrict__ wf1, const float* __restrict__ wb1,
                            const float* __restrict__ bf1, const float* __restrict__ bb1,
                            const int* __restrict__ masks) {
    int i = blockIdx.x * blockDim.x + threadIdx.x;
    if (i < G16 * 400) {
        int n = i / 400, k = i % 400;
        int nn = (n < 800) ? n : n - 800;
        float v0 = 0.f, v1 = 0.f;
        if (k < 360) {
            const float* W = (n < 800) ? wf0 : wb0;
            v0 = to_tf32(W[(size_t)nn * 360 + k]);
        }
        {
            const float* W = (n < 800) ? wf1 : wb1;
            v1 = to_tf32(W[(size_t)nn * 400 + k]);
        }
        d_wcat[0][i] = v0;
        d_wcat[1][i] = v1;
    }
    if (i < G16) {
        d_bcat[0][i] = (i < 800) ? bf0[i] : bb0[i - 800];
        d_bcat[1][i] = (i < 800) ? bf1[i] : bb1[i - 800];
    }
    if (i < Tt * Bsz) {
        int t = i / Bsz, b = i % Bsz;
        d_mt[i] = (masks[b * Tt + t] == 0) ? 1.f : 0.f;
    }
    if (i < 2 * 2 * Bsz * Hh) ((float*)d_h)[i] = 0.f;
    if (i < 512) d_barc3[i] = 0;
}

// ---------------- init between layers: reset h + barriers ----------------
__global__ void init2_kernel() {
    int i = blockIdx.x * blockDim.x + threadIdx.x;
    if (i < 2 * 2 * Bsz * Hh) ((float*)d_h)[i] = 0.f;
    if (i < 512) d_barc3[i] = 0;
}

// ---------------- TF32 GEMM: d_g[32768,1600] = A[32768,400] @ Wcat^T + bias -
__global__ __launch_bounds__(512, 1)
void gemm_tf32(int asel, int layer) {
    extern __shared__ float smg[];
    float* Abuf[2] = { smg, smg + 5632 };              // 128*44 each
    float* Bbuf[2] = { smg + 11264, smg + 18304 };     // 160*44 each
    const float* A = asel ? d_x1 : d_x0;
    const float* Wc = d_wcat[layer];
    const float* bc = d_bcat[layer];

    const int tid = threadIdx.x;
    const int lane = tid & 31, w = tid >> 5;
    const int wm = w & 3, wn = w >> 2;
    const int g = lane >> 2, tg = lane & 3;
    const int m0 = blockIdx.y * 128, n0 = blockIdx.x * 160;

    uint32_t sA[2], sB[2];
    sA[0] = (uint32_t)__cvta_generic_to_shared(Abuf[0]);
    sA[1] = (uint32_t)__cvta_generic_to_shared(Abuf[1]);
    sB[0] = (uint32_t)__cvta_generic_to_shared(Bbuf[0]);
    sB[1] = (uint32_t)__cvta_generic_to_shared(Bbuf[1]);

    float acc[2][5][4];
#pragma unroll
    for (int i = 0; i < 2; i++)
#pragma unroll
        for (int j = 0; j < 5; j++)
#pragma unroll
            for (int r = 0; r < 4; r++) acc[i][j][r] = 0.f;

#define STAGE(IT, BUF) do {                                                    \
        int k0 = (IT) * 40;                                                    \
        for (int i = tid; i < 1280; i += 512) {                                \
            int row = i / 10, c4 = (i % 10) * 4;                               \
            cp16(sA[BUF] + (uint32_t)(row * 44 + c4) * 4,                      \
                 A + (size_t)(m0 + row) * 400 + k0 + c4);                      \
        }                                                                      \
        for (int i = tid; i < 1600; i += 512) {                                \
            int row = i / 10, c4 = (i % 10) * 4;                               \
            cp16(sB[BUF] + (uint32_t)(row * 44 + c4) * 4,                      \
                 Wc + (size_t)(n0 + row) * 400 + k0 + c4);                     \
        }                                                                      \
        asm volatile("cp.async.commit_group;");                                \
    } while (0)

    STAGE(0, 0);

    for (int it = 0; it < 10; it++) {
        const int cur = it & 1;
        asm volatile("cp.async.wait_group 0;");
        __syncthreads();
        if (it < 9) STAGE(it + 1, cur ^ 1);

        const float* As = Abuf[cur];
        const float* Bs = Bbuf[cur];
#pragma unroll
        for (int ks = 0; ks < 5; ks++) {
            const int kb = ks * 8;
            uint32_t afr[2][4];
#pragma unroll
            for (int mi = 0; mi < 2; mi++) {
                int m = wm * 32 + mi * 16 + g;
                afr[mi][0] = __float_as_uint(As[m * 44 + kb + tg]);
                afr[mi][1] = __float_as_uint(As[(m + 8) * 44 + kb + tg]);
                afr[mi][2] = __float_as_uint(As[m * 44 + kb + tg + 4]);
                afr[mi][3] = __float_as_uint(As[(m + 8) * 44 + kb + tg + 4]);
            }
            uint32_t bfr[5][2];
#pragma unroll
            for (int nj = 0; nj < 5; nj++) {
                int n = wn * 40 + nj * 8 + g;
                bfr[nj][0] = __float_as_uint(Bs[n * 44 + kb + tg]);
                bfr[nj][1] = __float_as_uint(Bs[n * 44 + kb + tg + 4]);
            }
#pragma unroll
            for (int mi = 0; mi < 2; mi++)
#pragma unroll
                for (int nj = 0; nj < 5; nj++)
                    mma_tf32(acc[mi][nj], afr[mi], bfr[nj]);
        }
    }
#undef STAGE

#pragma unroll
    for (int mi = 0; mi < 2; mi++) {
        int mrow = m0 + wm * 32 + mi * 16 + g;
#pragma unroll
        for (int nj = 0; nj < 5; nj++) {
            int ncol = n0 + wn * 40 + nj * 8 + 2 * tg;
            float bx = bc[ncol], by = bc[ncol + 1];
            *(float2*)(d_g + (size_t)mrow * G16 + ncol) =
                make_float2(acc[mi][nj][0] + bx, acc[mi][nj][1] + by);
            *(float2*)(d_g + (size_t)(mrow + 8) * G16 + ncol) =
                make_float2(acc[mi][nj][2] + bx, acc[mi][nj][3] + by);
        }
    }
}

// ---------------- persistent tensor-core bidirectional LSTM ----------------
// 100 blocks = 2 dir x 2 batch-halves x 25 u-slices. 128 thr (4 warps).
// Warp w owns global batch rows [mh*64+16w, +16); block owns 8 hidden units.
// Warp-group = (dir, mh, w): 25 producer/consumer blocks, per-lane counters.
#define NDB 25

__global__ __launch_bounds__(128, 1)
void lstm_layer(const float* __restrict__ Whhf, const float* __restrict__ Whhb, int layer) {
    extern __shared__ float sm[];
    float* hs = sm;            // [64][212] = 13568 floats (block's 64 batch rows)
    float* Wp = sm + 13568;    // [32][206] = 6592 floats

    const int tid = threadIdx.x;
    const int lane = tid & 31, w = tid >> 5;   // w in 0..3
    const int bx = blockIdx.x;
    const int dir = bx / (2 * NDB);
    const int mh  = (bx / NDB) & 1;
    const int u0  = (bx % NDB) * 8;
    const float* Whh = dir ? Whhb : Whhf;
    float* out = layer ? d_rnn : d_x1;
    float* hbuf0 = d_h[dir][0];
    float* hbuf1 = d_h[dir][1];

    // pack W_hh slice, tf32, pair-packed for float2 B-fragment loads
    for (int i = tid; i < 32 * 200; i += 128) {
        int n = i / 200, p = i % 200;
        int k0 = p >> 3, r = p & 7, tg2 = r >> 1, c = r & 1;
        int k = k0 * 8 + tg2 + 4 * c;
        int grow = (n >> 3) * Hh + u0 + (n & 7);
        Wp[n * 206 + p] = to_tf32(Whh[(size_t)grow * Hh + k]);
    }
    __syncthreads();

    const int m0 = mh * 64 + w * 16;   // global batch base for this warp
    const int lr0 = w * 16;            // local hs row base
    const int g = lane >> 2, tg = lane & 3;
    unsigned* bar = d_barc3 + (((dir * 2 + mh) * 4 + w) * 32);
    const uint32_t hs_base = (uint32_t)__cvta_generic_to_shared(hs);

    float cst[4] = {0.f, 0.f, 0.f, 0.f};
    float hreg[4] = {0.f, 0.f, 0.f, 0.f};

    // prefetch gates + mask for step 0
    float2 gx[4][2];
    float mk0, mk1;
    {
        int t0 = dir ? Tt - 1 : 0;
#pragma unroll
        for (int j = 0; j < 4; j++) {
            gx[j][0] = *(const float2*)&d_g[(size_t)((m0 + g) * Tt + t0) * G16 +
                                            dir * 800 + j * 200 + u0 + 2 * tg];
            gx[j][1] = *(const float2*)&d_g[(size_t)((m0 + g + 8) * Tt + t0) * G16 +
                                            dir * 800 + j * 200 + u0 + 2 * tg];
        }
        mk0 = d_mt[t0 * Bsz + m0 + g];
        mk1 = d_mt[t0 * Bsz + m0 + g + 8];
    }

    for (int s = 0; s < Tt; s++) {
        const int t = dir ? (Tt - 1 - s) : s;
        const float* hcur = (s & 1) ? hbuf1 : hbuf0;
        float* hnxt = (s & 1) ? hbuf0 : hbuf1;

        // wait: all 25 blocks of this warp-group done with step s-1
        if (s) {
            unsigned tgt = (unsigned)NDB * (unsigned)s;
            while (ld_acq(&bar[lane]) < tgt) {}
        }
        __syncwarp();

        // stage this warp's 16 batch rows of h_prev (L1-bypassed)
        for (int i = lane; i < 800; i += 32) {
            int r16 = i / 50, c4 = (i % 50) * 4;
            cp16(hs_base + (uint32_t)((lr0 + r16) * 212 + c4) * 4,
                 hcur + (size_t)(m0 + r16) * Hh + c4);
        }
        asm volatile("cp.async.commit_group;");
        asm volatile("cp.async.wait_group 0;");
        __syncwarp();

        float acc[4][4];
#pragma unroll
        for (int j = 0; j < 4; j++)
#pragma unroll
            for (int r = 0; r < 4; r++) acc[j][r] = 0.f;

#pragma unroll
        for (int ik = 0; ik < 25; ik++) {
            const int kb = ik * 8;
            uint32_t a[4];
            a[0] = __float_as_uint(hs[(lr0 + g) * 212 + kb + tg]);
            a[1] = __float_as_uint(hs[(lr0 + g + 8) * 212 + kb + tg]);
            a[2] = __float_as_uint(hs[(lr0 + g) * 212 + kb + tg + 4]);
            a[3] = __float_as_uint(hs[(lr0 + g + 8) * 212 + kb + tg + 4]);
#pragma unroll
            for (int j = 0; j < 4; j++) {
                float2 bp = *(const float2*)&Wp[(j * 8 + g) * 206 + kb + tg * 2];
                uint32_t bb[2] = { __float_as_uint(bp.x), __float_as_uint(bp.y) };
                mma_tf32(acc[j], a, bb);
            }
        }

#pragma unroll
        for (int j = 0; j < 4; j++) {
            acc[j][0] += gx[j][0].x; acc[j][1] += gx[j][0].y;
            acc[j][2] += gx[j][1].x; acc[j][3] += gx[j][1].y;
        }

        // cell update in registers
        float ho[4];
#pragma unroll
        for (int r = 0; r < 4; r++) {
            float m = (r >> 1) ? mk1 : mk0;
            float iv = sig_(acc[0][r]);
            float fv = sig_(acc[1][r]);
            float gv = tanh_(acc[2][r]);
            float ov = sig_(acc[3][r]);
            float cn = fv * cst[r] + iv * gv;
            float hn = ov * tanh_(cn);
            float hnew = m * hn + (1.f - m) * hreg[r];
            cst[r] = m * cn + (1.f - m) * cst[r];
            hreg[r] = hnew;
            ho[r] = m * hn;
        }

        // store h_next (tf32, paired)
        *(float2*)&hnxt[(size_t)(m0 + g) * Hh + u0 + 2 * tg] =
            make_float2(to_tf32(hreg[0]), to_tf32(hreg[1]));
        *(float2*)&hnxt[(size_t)(m0 + g + 8) * Hh + u0 + 2 * tg] =
            make_float2(to_tf32(hreg[2]), to_tf32(hreg[3]));

        // release: each lane orders its own stores (spread-address REDG)
        red_rel(&bar[lane]);

        // ---- tail (off other blocks' critical path) ----
        {
            float2 o0, o1;
            if (layer) { o0 = make_float2(ho[0], ho[1]); o1 = make_float2(ho[2], ho[3]); }
            else { o0 = make_float2(to_tf32(ho[0]), to_tf32(ho[1]));
                   o1 = make_float2(to_tf32(ho[2]), to_tf32(ho[3])); }
            *(float2*)&out[(size_t)((m0 + g) * Tt + t) * IN1 + dir * Hh + u0 + 2 * tg] = o0;
            *(float2*)&out[(size_t)((m0 + g + 8) * Tt + t) * IN1 + dir * Hh + u0 + 2 * tg] = o1;
        }
        if (layer && s == Tt - 1) {
            *(float2*)&d_hfin[dir][(m0 + g) * Hh + u0 + 2 * tg] =
                make_float2(hreg[0], hreg[1]);
            *(float2*)&d_hfin[dir][(m0 + g + 8) * Hh + u0 + 2 * tg] =
                make_float2(hreg[2], hreg[3]);
        }
        if (s < Tt - 1) {
            int tn = dir ? (Tt - 2 - s) : (s + 1);
#pragma unroll
            for (int j = 0; j < 4; j++) {
                gx[j][0] = *(const float2*)&d_g[(size_t)((m0 + g) * Tt + tn) * G16 +
                                                dir * 800 + j * 200 + u0 + 2 * tg];
                gx[j][1] = *(const float2*)&d_g[(size_t)((m0 + g + 8) * Tt + tn) * G16 +
                                                dir * 800 + j * 200 + u0 + 2 * tg];
            }
            mk0 = d_mt[tn * Bsz + m0 + g];
            mk1 = d_mt[tn * Bsz + m0 + g + 8];
        }
    }
}

// ---------------- span sums + queries ----------------
__global__ void span_kernel(const int* __restrict__ masks, const int* __restrict__ subj,
                            const int* __restrict__ obj) {
    int b = blockIdx.x;
    __shared__ float ssel[Tt];
    __shared__ float osel[Tt];
    for (int t = threadIdx.x; t < Tt; t += blockDim.x) {
        int m = masks[b * Tt + t];
        ssel[t] = (subj[b * Tt + t] + m == 0) ? 1.f : 0.f;
        osel[t] = (obj[b * Tt + t] + m == 0) ? 1.f : 0.f;
    }
    __syncthreads();
    for (int f = threadIdx.x; f < IN1; f += blockDim.x) {
        float ss = 0.f, os = 0.f;
        for (int t = 0; t < Tt; t++) {
            float v = d_rnn[(size_t)(b * Tt + t) * IN1 + f];
            ss += v * ssel[t];
            os += v * osel[t];
        }
        d_q[0][b * IN1 + f] = os;
        d_q[1][b * IN1 + f] = ss;
        d_q[2][b * IN1 + f] = (f < Hh) ? d_hfin[1][b * Hh + f]
                                       : d_hfin[0][b * Hh + f - Hh];
    }
}

// ---------------- attention pooling (warp-per-t scoring, coalesced) --------
__global__ void attn_kernel(const int* __restrict__ masks) {
    int b = blockIdx.x / 3, qi = blockIdx.x % 3;
    __shared__ float qv[IN1];
    __shared__ float ps[Tt];
    __shared__ float red[256];
    int tid = threadIdx.x, lane = tid & 31, w = tid >> 5;
    for (int f = tid; f < IN1; f += 256) qv[f] = d_q[qi][b * IN1 + f];
    __syncthreads();

    for (int t = w; t < Tt; t += 8) {
        const float* row = d_rnn + (size_t)(b * Tt + t) * IN1;
        float sc = 0.f;
        for (int k = lane; k < IN1; k += 32) sc += qv[k] * row[k];
        for (int o = 16; o; o >>= 1) sc += __shfl_down_sync(0xffffffffu, sc, o);
        if (lane == 0) ps[t] = sc * 0.05f;
    }
    __syncthreads();

    float sc = ps[tid];
    if (masks[b * Tt + tid] != 0) sc = -1e9f;

    red[tid] = sc; __syncthreads();
    for (int o = 128; o; o >>= 1) { if (tid < o) red[tid] = fmaxf(red[tid], red[tid + o]); __syncthreads(); }
    float mx = red[0]; __syncthreads();
    float e = __expf(sc - mx);
    red[tid] = e; __syncthreads();
    for (int o = 128; o; o >>= 1) { if (tid < o) red[tid] += red[tid + o]; __syncthreads(); }
    float inv = 1.f / red[0];
    ps[tid] = e * inv;
    __syncthreads();

    for (int f = tid; f < IN1; f += 256) {
        float a = 0.f;
        for (int t = 0; t < Tt; t++) a += ps[t] * d_rnn[(size_t)(b * Tt + t) * IN1 + f];
        d_att[qi][b * IN1 + f] = a;
    }
}

// ---------------- final MLP head ----------------
__global__ void final_kernel(const float* __restrict__ wo_w, const float* __restrict__ wo_b,
                             const float* __restrict__ ws_w, const float* __restrict__ ws_b,
                             const float* __restrict__ wg_w, const float* __restrict__ wg_b,
                             const float* __restrict__ cls_w, const float* __restrict__ cls_b,
                             float* __restrict__ outp) {
    int b = blockIdx.x;
    __shared__ float hv[Hh];
    int j = threadIdx.x;
    if (j < Hh) {
        float a = wo_b[j] + ws_b[j] + wg_b[j];
        const float* o = &d_att[0][b * IN1];
        const float* s = &d_att[1][b * IN1];
        const float* gq = &d_att[2][b * IN1];
        const float* wo = wo_w + (size_t)j * IN1;
        const float* ws = ws_w + (size_t)j * IN1;
        const float* wg = wg_w + (size_t)j * IN1;
        for (int k = 0; k < IN1; k++)
            a += o[k] * wo[k] + s[k] * ws[k] + gq[k] * wg[k];
        hv[j] = fmaxf(a, 0.f);
    }
    __syncthreads();
    if (j < 64) {
        int n = j >> 5, lane = j & 31;
        float p = 0.f;
        for (int k = lane; k < Hh; k += 32) p += hv[k] * cls_w[n * Hh + k];
        for (int o = 16; o; o >>= 1) p += __shfl_down_sync(0xffffffffu, p, o);
        if (lane == 0) outp[b * NCLASS + n] = p + cls_b[n];
    }
}

// ---------------- launcher ----------------
extern "C" void kernel_launch(void* const* d_in, const int* in_sizes, int n_in,
                              void* d_out, int out_size) {
    const int*   words    = (const int*)d_in[0];
    const int*   masks    = (const int*)d_in[1];
    const int*   pos      = (const int*)d_in[2];
    const int*   ner      = (const int*)d_in[3];
    const int*   subj_pos = (const int*)d_in[4];
    const int*   obj_pos  = (const int*)d_in[5];
    const float* emb_w    = (const float*)d_in[6];
    const float* pos_w    = (const float*)d_in[7];
    const float* ner_w    = (const float*)d_in[8];
    const float* w_ih_l0f = (const float*)d_in[9];
    const float* w_hh_l0f = (const float*)d_in[10];
    const float* b_l0f    = (const float*)d_in[11];
    const float* w_ih_l0b = (const float*)d_in[12];
    const float* w_hh_l0b = (const float*)d_in[13];
    const float* b_l0b    = (const float*)d_in[14];
    const float* w_ih_l1f = (const float*)d_in[15];
    const float* w_hh_l1f = (const float*)d_in[16];
    const float* b_l1f    = (const float*)d_in[17];
    const float* w_ih_l1b = (const float*)d_in[18];
    const float* w_hh_l1b = (const float*)d_in[19];
    const float* b_l1b    = (const float*)d_in[20];
    const float* wo_w     = (const float*)d_in[21];
    const float* wo_b     = (const float*)d_in[22];
    const float* ws_w     = (const float*)d_in[23];
    const float* ws_b     = (const float*)d_in[24];
    const float* wg_w     = (const float*)d_in[25];
    const float* wg_b     = (const float*)d_in[26];
    const float* cls_w    = (const float*)d_in[27];
    const float* cls_b    = (const float*)d_in[28];

    static const int GEMM_SMEM = 25344 * 4;   // 101376 B
    static const int LSTM_SMEM = 20160 * 4;   // 80640 B
    cudaFuncSetAttribute(gemm_tf32, cudaFuncAttributeMaxDynamicSharedMemorySize, GEMM_SMEM);
    cudaFuncSetAttribute(lstm_layer, cudaFuncAttributeMaxDynamicSharedMemorySize, LSTM_SMEM);

    dim3 ggrid(10, 256);   // N=1600/160, M=32768/128
    int ppgrid = (G16 * 400 + 255) / 256;

    embed_kernel<<<(BT * 400 + 255) / 256, 256>>>(words, pos, ner, emb_w, pos_w, ner_w); // 0
    prep_kernel<<<ppgrid, 256>>>(w_ih_l0f, w_ih_l0b, b_l0f, b_l0b,
                                 w_ih_l1f, w_ih_l1b, b_l1f, b_l1b, masks);               // 1
    gemm_tf32<<<ggrid, 512, GEMM_SMEM>>>(0, 0);                                           // 2
    lstm_layer<<<4 * NDB, 128, LSTM_SMEM>>>(w_hh_l0f, w_hh_l0b, 0);                       // 3
    gemm_tf32<<<ggrid, 512, GEMM_SMEM>>>(1, 1);                                           // 4
    init2_kernel<<<(2 * 2 * Bsz * Hh + 255) / 256, 256>>>();                              // 5
    lstm_layer<<<4 * NDB, 128, LSTM_SMEM>>>(w_hh_l1f, w_hh_l1b, 1);                       // 6
    span_kernel<<<Bsz, 256>>>(masks, subj_pos, obj_pos);                                  // 7
    attn_kernel<<<Bsz * 3, 256>>>(masks);                                                 // 8
    final_kernel<<<Bsz, 256>>>(wo_w, wo_b, ws_w, ws_b, wg_w, wg_b, cls_w, cls_b,
                               (float*)d_out);                                            // 9
}